// round 4
// baseline (speedup 1.0000x reference)
#include <cuda_runtime.h>
#include <cuda_bf16.h>

// LinearNavigator fused: preproc -> LSTM(2->20) -> LSTM(20->20) -> head -> x[1..5]
// B = 1048576, H = 20.
// Weights live in __constant__ memory -> uniform-register loads (LDCU) on the
// separate constant port; NO shared memory, so L1TEX handles only global h/c IO.
// Output: out[B,5], h_stack[2,B,20], c_stack[2,B,20]

#define NB 1048576
#define HDIM 20

struct NaviConsts {
    float Wih1[80 * 2];
    float Whh1[80 * HDIM];
    float Wih2[80 * HDIM];
    float Whh2[80 * HDIM];
    float bih1[80];
    float bhh1[80];
    float bih2[80];
    float bhh2[80];
    float Wo[HDIM];
    float bo[1];
};

__constant__ NaviConsts cw;

__device__ __forceinline__ float sigmoid_(float x) {
    return __fdividef(1.0f, 1.0f + __expf(-x));
}
__device__ __forceinline__ float tanh_(float x) {
    float e = __expf(2.0f * x);
    return 1.0f - __fdividef(2.0f, e + 1.0f);
}

__global__ __launch_bounds__(128)
void navi_kernel(const float* __restrict__ inp,
                 const float* __restrict__ hidden,
                 const float* __restrict__ cell,
                 float* __restrict__ out)
{
    const size_t b = (size_t)blockIdx.x * 128 + threadIdx.x;

    // ---------------- preproc ----------------
    const float v  = inp[b];
    const float av = fabsf(v);
    const float THR = 4.5399929762484854e-05f;  // exp(-10)
    const float E10 = 22026.465794806718f;      // exp(10)
    float x0, x1;
    if (av >= THR) {
        x0 = __logf(av + 1e-8f) * 0.1f;
        x1 = (v > 0.0f) ? 1.0f : -1.0f;
    } else {
        x0 = -1.0f;
        x1 = E10 * v;
    }

    // ---------------- load layer-1 state (vectorized) ----------------
    float h0[HDIM], c0[HDIM];
    {
        const float4* hp = reinterpret_cast<const float4*>(hidden + b * HDIM);
        const float4* cp = reinterpret_cast<const float4*>(cell   + b * HDIM);
        #pragma unroll
        for (int q = 0; q < 5; q++) {
            float4 hv = hp[q];
            h0[4*q+0] = hv.x; h0[4*q+1] = hv.y; h0[4*q+2] = hv.z; h0[4*q+3] = hv.w;
            float4 cv = cp[q];
            c0[4*q+0] = cv.x; c0[4*q+1] = cv.y; c0[4*q+2] = cv.z; c0[4*q+3] = cv.w;
        }
    }

    // ---------------- LSTM layer 1 ----------------
    float hn1[HDIM];
    #pragma unroll 1
    for (int j = 0; j < HDIM; j++) {
        float gi = cw.bih1[j]      + cw.bhh1[j]      + x0 * cw.Wih1[2*j]        + x1 * cw.Wih1[2*j + 1];
        float gf = cw.bih1[j + 20] + cw.bhh1[j + 20] + x0 * cw.Wih1[2*(j+20)]   + x1 * cw.Wih1[2*(j+20) + 1];
        float gg = cw.bih1[j + 40] + cw.bhh1[j + 40] + x0 * cw.Wih1[2*(j+40)]   + x1 * cw.Wih1[2*(j+40) + 1];
        float go = cw.bih1[j + 60] + cw.bhh1[j + 60] + x0 * cw.Wih1[2*(j+60)]   + x1 * cw.Wih1[2*(j+60) + 1];
        const float* wi = &cw.Whh1[j * HDIM];
        const float* wf = &cw.Whh1[(j + 20) * HDIM];
        const float* wg = &cw.Whh1[(j + 40) * HDIM];
        const float* wo = &cw.Whh1[(j + 60) * HDIM];
        #pragma unroll
        for (int k = 0; k < HDIM; k++) {
            const float hk = h0[k];
            gi += hk * wi[k];
            gf += hk * wf[k];
            gg += hk * wg[k];
            go += hk * wo[k];
        }
        const float cn = sigmoid_(gf) * c0[j] + sigmoid_(gi) * tanh_(gg);
        hn1[j] = sigmoid_(go) * tanh_(cn);
        c0[j] = cn;  // staging for c0_new
    }

    // ---------------- store layer-1 outputs ----------------
    {
        float4* hp = reinterpret_cast<float4*>(out + (size_t)5 * NB + b * HDIM);
        float4* cp = reinterpret_cast<float4*>(out + (size_t)5 * NB + (size_t)2 * NB * HDIM + b * HDIM);
        #pragma unroll
        for (int q = 0; q < 5; q++) {
            hp[q] = make_float4(hn1[4*q], hn1[4*q+1], hn1[4*q+2], hn1[4*q+3]);
            cp[q] = make_float4(c0[4*q],  c0[4*q+1],  c0[4*q+2],  c0[4*q+3]);
        }
    }

    // ---------------- load layer-2 state ----------------
    float h1[HDIM], c1[HDIM];
    {
        const float4* hp = reinterpret_cast<const float4*>(hidden + (size_t)NB * HDIM + b * HDIM);
        const float4* cp = reinterpret_cast<const float4*>(cell   + (size_t)NB * HDIM + b * HDIM);
        #pragma unroll
        for (int q = 0; q < 5; q++) {
            float4 hv = hp[q];
            h1[4*q+0] = hv.x; h1[4*q+1] = hv.y; h1[4*q+2] = hv.z; h1[4*q+3] = hv.w;
            float4 cv = cp[q];
            c1[4*q+0] = cv.x; c1[4*q+1] = cv.y; c1[4*q+2] = cv.z; c1[4*q+3] = cv.w;
        }
    }

    // ---------------- LSTM layer 2 ----------------
    float hn2[HDIM];
    #pragma unroll 1
    for (int j = 0; j < HDIM; j++) {
        float gi = cw.bih2[j]      + cw.bhh2[j];
        float gf = cw.bih2[j + 20] + cw.bhh2[j + 20];
        float gg = cw.bih2[j + 40] + cw.bhh2[j + 40];
        float go = cw.bih2[j + 60] + cw.bhh2[j + 60];
        const float* xi = &cw.Wih2[j * HDIM];
        const float* xf = &cw.Wih2[(j + 20) * HDIM];
        const float* xg = &cw.Wih2[(j + 40) * HDIM];
        const float* xo = &cw.Wih2[(j + 60) * HDIM];
        const float* ri = &cw.Whh2[j * HDIM];
        const float* rf = &cw.Whh2[(j + 20) * HDIM];
        const float* rg = &cw.Whh2[(j + 40) * HDIM];
        const float* ro = &cw.Whh2[(j + 60) * HDIM];
        #pragma unroll
        for (int k = 0; k < HDIM; k++) {
            const float xk = hn1[k];
            const float hk = h1[k];
            gi += xk * xi[k] + hk * ri[k];
            gf += xk * xf[k] + hk * rf[k];
            gg += xk * xg[k] + hk * rg[k];
            go += xk * xo[k] + hk * ro[k];
        }
        const float cn = sigmoid_(gf) * c1[j] + sigmoid_(gi) * tanh_(gg);
        hn2[j] = sigmoid_(go) * tanh_(cn);
        c1[j] = cn;
    }

    // ---------------- output head ----------------
    float o = cw.bo[0];
    #pragma unroll
    for (int k = 0; k < HDIM; k++) o += hn2[k] * cw.Wo[k];

    // ---------------- stores ----------------
    float* out5 = out + b * 5;
    #pragma unroll
    for (int s = 0; s < 5; s++) out5[s] = o * (float)(s + 1);

    float* hbase = out + (size_t)5 * NB;
    float* cbase = out + (size_t)5 * NB + (size_t)2 * NB * HDIM;
    float4* h1p = reinterpret_cast<float4*>(hbase + (size_t)NB * HDIM + b * HDIM);
    float4* c1p = reinterpret_cast<float4*>(cbase + (size_t)NB * HDIM + b * HDIM);
    #pragma unroll
    for (int q = 0; q < 5; q++) {
        h1p[q] = make_float4(hn2[4*q], hn2[4*q+1], hn2[4*q+2], hn2[4*q+3]);
        c1p[q] = make_float4(c1[4*q],  c1[4*q+1],  c1[4*q+2],  c1[4*q+3]);
    }
}

extern "C" void kernel_launch(void* const* d_in, const int* in_sizes, int n_in,
                              void* d_out, int out_size) {
    const float* inp    = (const float*)d_in[0];
    const float* hidden = (const float*)d_in[1];
    const float* cell   = (const float*)d_in[2];

    // Stage all weights into constant memory (async D2D copies: graph-capturable).
    cudaMemcpyToSymbolAsync(cw, d_in[3],  sizeof(float) * 160,       offsetof(NaviConsts, Wih1), cudaMemcpyDeviceToDevice, 0);
    cudaMemcpyToSymbolAsync(cw, d_in[4],  sizeof(float) * 1600,      offsetof(NaviConsts, Whh1), cudaMemcpyDeviceToDevice, 0);
    cudaMemcpyToSymbolAsync(cw, d_in[5],  sizeof(float) * 80,        offsetof(NaviConsts, bih1), cudaMemcpyDeviceToDevice, 0);
    cudaMemcpyToSymbolAsync(cw, d_in[6],  sizeof(float) * 80,        offsetof(NaviConsts, bhh1), cudaMemcpyDeviceToDevice, 0);
    cudaMemcpyToSymbolAsync(cw, d_in[7],  sizeof(float) * 1600,      offsetof(NaviConsts, Wih2), cudaMemcpyDeviceToDevice, 0);
    cudaMemcpyToSymbolAsync(cw, d_in[8],  sizeof(float) * 1600,      offsetof(NaviConsts, Whh2), cudaMemcpyDeviceToDevice, 0);
    cudaMemcpyToSymbolAsync(cw, d_in[9],  sizeof(float) * 80,        offsetof(NaviConsts, bih2), cudaMemcpyDeviceToDevice, 0);
    cudaMemcpyToSymbolAsync(cw, d_in[10], sizeof(float) * 80,        offsetof(NaviConsts, bhh2), cudaMemcpyDeviceToDevice, 0);
    cudaMemcpyToSymbolAsync(cw, d_in[11], sizeof(float) * HDIM,      offsetof(NaviConsts, Wo),   cudaMemcpyDeviceToDevice, 0);
    cudaMemcpyToSymbolAsync(cw, d_in[12], sizeof(float) * 1,         offsetof(NaviConsts, bo),   cudaMemcpyDeviceToDevice, 0);

    float* out = (float*)d_out;
    const int threads = 128;
    const int blocks = NB / threads;
    navi_kernel<<<blocks, threads>>>(inp, hidden, cell, out);
}

// round 5
// speedup vs baseline: 2.8026x; 2.8026x over previous
#include <cuda_runtime.h>
#include <cuda_fp16.h>

// LinearNavigator, two-pass, 2 elements/thread packed in __half2 (HFMA2 math,
// fp32 partial-combine + fp32 activations).
// B = 1048576, H = 20.
// out layout: out[B,5], h_stack[2,B,20], c_stack[2,B,20]

#define NB 1048576
#define HDIM 20
#define HBASE ((size_t)5 * NB)
#define CBASE ((size_t)5 * NB + (size_t)2 * NB * HDIM)

__device__ __forceinline__ float sigmoid_(float x) {
    return __fdividef(1.0f, 1.0f + __expf(-x));
}
__device__ __forceinline__ float tanh_(float x) {
    float e = __expf(2.0f * x);
    return 1.0f - __fdividef(2.0f, e + 1.0f);
}
__device__ __forceinline__ __half2 H2(unsigned u) {
    return *reinterpret_cast<__half2*>(&u);
}

// ---------------------------------------------------------------------------
// Pass 1: preproc + LSTM layer 1. Writes h_stack[0], c_stack[0].
// ---------------------------------------------------------------------------
__global__ __launch_bounds__(128)
void navi_l1(const float* __restrict__ inp, const float* __restrict__ hidden,
             const float* __restrict__ cell,
             const float* __restrict__ W_ih1, const float* __restrict__ W_hh1,
             const float* __restrict__ b_ih1, const float* __restrict__ b_hh1,
             float* __restrict__ out)
{
    __shared__ __align__(16) __half2 sW[80 * HDIM];  // Whh1, splatted (w,w)
    __shared__ float sWih[160];                      // Wih1 fp32 (2 cols)
    __shared__ float sb[80];

    const int t = threadIdx.x;
    for (int i = t; i < 1600; i += 128) sW[i] = __float2half2_rn(W_hh1[i]);
    for (int i = t; i < 160;  i += 128) sWih[i] = W_ih1[i];
    for (int i = t; i < 80;   i += 128) sb[i] = b_ih1[i] + b_hh1[i];
    __syncthreads();

    const size_t b0 = ((size_t)blockIdx.x * 128 + t) * 2;

    // preproc, both elements (fp32)
    const float THR = 4.5399929762484854e-05f;  // exp(-10)
    const float E10 = 22026.465794806718f;      // exp(10)
    float x0a, x1a, x0b, x1b;
    {
        float v = inp[b0];
        float av = fabsf(v);
        if (av >= THR) { x0a = __logf(av + 1e-8f) * 0.1f; x1a = (v > 0.0f) ? 1.0f : -1.0f; }
        else           { x0a = -1.0f; x1a = E10 * v; }
        v = inp[b0 + 1];
        av = fabsf(v);
        if (av >= THR) { x0b = __logf(av + 1e-8f) * 0.1f; x1b = (v > 0.0f) ? 1.0f : -1.0f; }
        else           { x0b = -1.0f; x1b = E10 * v; }
    }

    // h0 for both elements, packed (elemA = low, elemB = high)
    __half2 hp[HDIM];
    {
        const float4* hA = reinterpret_cast<const float4*>(hidden + b0 * HDIM);
        #pragma unroll
        for (int q = 0; q < 5; q++) {
            float4 A = hA[q], Bv = hA[q + 5];
            hp[4*q+0] = __floats2half2_rn(A.x, Bv.x);
            hp[4*q+1] = __floats2half2_rn(A.y, Bv.y);
            hp[4*q+2] = __floats2half2_rn(A.z, Bv.z);
            hp[4*q+3] = __floats2half2_rn(A.w, Bv.w);
        }
    }

    const float4* cIn = reinterpret_cast<const float4*>(cell + b0 * HDIM);
    float4* hOut = reinterpret_cast<float4*>(out + HBASE + b0 * HDIM);
    float4* cOut = reinterpret_cast<float4*>(out + CBASE + b0 * HDIM);

    #pragma unroll 1
    for (int jj = 0; jj < 5; jj++) {
        float4 cA = cIn[jj], cB = cIn[jj + 5];
        float4 hnA, hnB, cnA, cnB;
        float* cAv = (float*)&cA;  float* cBv = (float*)&cB;
        float* hnAv = (float*)&hnA; float* hnBv = (float*)&hnB;
        float* cnAv = (float*)&cnA; float* cnBv = (float*)&cnB;
        #pragma unroll
        for (int j2 = 0; j2 < 4; j2++) {
            const int j = jj * 4 + j2;
            float gAv[4], gBv[4];
            #pragma unroll
            for (int g = 0; g < 4; g++) {
                const int r = g * 20 + j;
                const uint4* W = reinterpret_cast<const uint4*>(sW + r * HDIM);
                uint4 w0 = W[0], w1 = W[1], w2 = W[2], w3 = W[3], w4 = W[4];
                unsigned wk[20] = {w0.x,w0.y,w0.z,w0.w, w1.x,w1.y,w1.z,w1.w,
                                   w2.x,w2.y,w2.z,w2.w, w3.x,w3.y,w3.z,w3.w,
                                   w4.x,w4.y,w4.z,w4.w};
                __half2 a0 = __hmul2(H2(wk[0]), hp[0]);
                #pragma unroll
                for (int k = 1; k < 10; k++) a0 = __hfma2(H2(wk[k]), hp[k], a0);
                __half2 a1 = __hmul2(H2(wk[10]), hp[10]);
                #pragma unroll
                for (int k = 11; k < 20; k++) a1 = __hfma2(H2(wk[k]), hp[k], a1);
                float2 p0 = __half22float2(a0), p1 = __half22float2(a1);
                const float bb = sb[r];
                const float wa = sWih[r * 2], wb = sWih[r * 2 + 1];
                gAv[g] = bb + p0.x + p1.x + x0a * wa + x1a * wb;
                gBv[g] = bb + p0.y + p1.y + x0b * wa + x1b * wb;
            }
            // gates: 0=i 1=f 2=g 3=o
            float cn = sigmoid_(gAv[1]) * cAv[j2] + sigmoid_(gAv[0]) * tanh_(gAv[2]);
            cnAv[j2] = cn;
            hnAv[j2] = sigmoid_(gAv[3]) * tanh_(cn);
            cn = sigmoid_(gBv[1]) * cBv[j2] + sigmoid_(gBv[0]) * tanh_(gBv[2]);
            cnBv[j2] = cn;
            hnBv[j2] = sigmoid_(gBv[3]) * tanh_(cn);
        }
        hOut[jj] = hnA; hOut[jj + 5] = hnB;
        cOut[jj] = cnA; cOut[jj + 5] = cnB;
    }
}

// ---------------------------------------------------------------------------
// Pass 2: LSTM layer 2 + head. Reads hn1 from out (h_stack[0]).
// ---------------------------------------------------------------------------
__global__ __launch_bounds__(128)
void navi_l2(const float* __restrict__ hidden, const float* __restrict__ cell,
             const float* __restrict__ W_ih2, const float* __restrict__ W_hh2,
             const float* __restrict__ b_ih2, const float* __restrict__ b_hh2,
             const float* __restrict__ W_out, const float* __restrict__ b_out,
             float* __restrict__ out)
{
    __shared__ __align__(16) __half2 sWx[80 * HDIM];  // Wih2 splat
    __shared__ __align__(16) __half2 sWh[80 * HDIM];  // Whh2 splat
    __shared__ float sb[80];
    __shared__ float sWo[HDIM];
    __shared__ float sbo;

    const int t = threadIdx.x;
    for (int i = t; i < 1600; i += 128) sWx[i] = __float2half2_rn(W_ih2[i]);
    for (int i = t; i < 1600; i += 128) sWh[i] = __float2half2_rn(W_hh2[i]);
    for (int i = t; i < 80;   i += 128) sb[i] = b_ih2[i] + b_hh2[i];
    for (int i = t; i < HDIM; i += 128) sWo[i] = W_out[i];
    if (t == 0) sbo = b_out[0];
    __syncthreads();

    const size_t b0 = ((size_t)blockIdx.x * 128 + t) * 2;

    // x = hn1 (from out), h = hidden[1], both packed half2
    __half2 xp[HDIM], hp[HDIM];
    {
        const float4* xA = reinterpret_cast<const float4*>(out + HBASE + b0 * HDIM);
        const float4* hA = reinterpret_cast<const float4*>(hidden + (size_t)NB * HDIM + b0 * HDIM);
        #pragma unroll
        for (int q = 0; q < 5; q++) {
            float4 A = xA[q], Bv = xA[q + 5];
            xp[4*q+0] = __floats2half2_rn(A.x, Bv.x);
            xp[4*q+1] = __floats2half2_rn(A.y, Bv.y);
            xp[4*q+2] = __floats2half2_rn(A.z, Bv.z);
            xp[4*q+3] = __floats2half2_rn(A.w, Bv.w);
            A = hA[q]; Bv = hA[q + 5];
            hp[4*q+0] = __floats2half2_rn(A.x, Bv.x);
            hp[4*q+1] = __floats2half2_rn(A.y, Bv.y);
            hp[4*q+2] = __floats2half2_rn(A.z, Bv.z);
            hp[4*q+3] = __floats2half2_rn(A.w, Bv.w);
        }
    }

    const float4* cIn = reinterpret_cast<const float4*>(cell + (size_t)NB * HDIM + b0 * HDIM);
    float4* hOut = reinterpret_cast<float4*>(out + HBASE + (size_t)NB * HDIM + b0 * HDIM);
    float4* cOut = reinterpret_cast<float4*>(out + CBASE + (size_t)NB * HDIM + b0 * HDIM);

    float oA = sbo, oB = sbo;

    #pragma unroll 1
    for (int jj = 0; jj < 5; jj++) {
        float4 cA = cIn[jj], cB = cIn[jj + 5];
        float4 hnA, hnB, cnA, cnB;
        float* cAv = (float*)&cA;  float* cBv = (float*)&cB;
        float* hnAv = (float*)&hnA; float* hnBv = (float*)&hnB;
        float* cnAv = (float*)&cnA; float* cnBv = (float*)&cnB;
        #pragma unroll
        for (int j2 = 0; j2 < 4; j2++) {
            const int j = jj * 4 + j2;
            float gAv[4], gBv[4];
            #pragma unroll
            for (int g = 0; g < 4; g++) {
                const int r = g * 20 + j;
                const uint4* Wx = reinterpret_cast<const uint4*>(sWx + r * HDIM);
                const uint4* Wh = reinterpret_cast<const uint4*>(sWh + r * HDIM);
                uint4 x0 = Wx[0], x1 = Wx[1], x2 = Wx[2], x3 = Wx[3], x4 = Wx[4];
                unsigned xk[20] = {x0.x,x0.y,x0.z,x0.w, x1.x,x1.y,x1.z,x1.w,
                                   x2.x,x2.y,x2.z,x2.w, x3.x,x3.y,x3.z,x3.w,
                                   x4.x,x4.y,x4.z,x4.w};
                uint4 h0 = Wh[0], h1 = Wh[1], h2 = Wh[2], h3 = Wh[3], h4 = Wh[4];
                unsigned hk[20] = {h0.x,h0.y,h0.z,h0.w, h1.x,h1.y,h1.z,h1.w,
                                   h2.x,h2.y,h2.z,h2.w, h3.x,h3.y,h3.z,h3.w,
                                   h4.x,h4.y,h4.z,h4.w};
                __half2 a0 = __hmul2(H2(xk[0]), xp[0]);
                #pragma unroll
                for (int k = 1; k < 20; k++) a0 = __hfma2(H2(xk[k]), xp[k], a0);
                __half2 a1 = __hmul2(H2(hk[0]), hp[0]);
                #pragma unroll
                for (int k = 1; k < 20; k++) a1 = __hfma2(H2(hk[k]), hp[k], a1);
                float2 p0 = __half22float2(a0), p1 = __half22float2(a1);
                const float bb = sb[r];
                gAv[g] = bb + p0.x + p1.x;
                gBv[g] = bb + p0.y + p1.y;
            }
            float cn = sigmoid_(gAv[1]) * cAv[j2] + sigmoid_(gAv[0]) * tanh_(gAv[2]);
            cnAv[j2] = cn;
            float hn = sigmoid_(gAv[3]) * tanh_(cn);
            hnAv[j2] = hn;
            oA += hn * sWo[j];
            cn = sigmoid_(gBv[1]) * cBv[j2] + sigmoid_(gBv[0]) * tanh_(gBv[2]);
            cnBv[j2] = cn;
            hn = sigmoid_(gBv[3]) * tanh_(cn);
            hnBv[j2] = hn;
            oB += hn * sWo[j];
        }
        hOut[jj] = hnA; hOut[jj + 5] = hnB;
        cOut[jj] = cnA; cOut[jj + 5] = cnB;
    }

    // out[B,5]
    float* o5 = out + b0 * 5;
    #pragma unroll
    for (int s = 0; s < 5; s++) {
        o5[s]     = oA * (float)(s + 1);
        o5[s + 5] = oB * (float)(s + 1);
    }
}

extern "C" void kernel_launch(void* const* d_in, const int* in_sizes, int n_in,
                              void* d_out, int out_size) {
    const float* inp    = (const float*)d_in[0];
    const float* hidden = (const float*)d_in[1];
    const float* cell   = (const float*)d_in[2];
    const float* W_ih1  = (const float*)d_in[3];
    const float* W_hh1  = (const float*)d_in[4];
    const float* b_ih1  = (const float*)d_in[5];
    const float* b_hh1  = (const float*)d_in[6];
    const float* W_ih2  = (const float*)d_in[7];
    const float* W_hh2  = (const float*)d_in[8];
    const float* b_ih2  = (const float*)d_in[9];
    const float* b_hh2  = (const float*)d_in[10];
    const float* W_out  = (const float*)d_in[11];
    const float* b_out  = (const float*)d_in[12];
    float* out = (float*)d_out;

    const int threads = 128;
    const int blocks = NB / (threads * 2);  // 2 elements per thread
    navi_l1<<<blocks, threads>>>(inp, hidden, cell, W_ih1, W_hh1, b_ih1, b_hh1, out);
    navi_l2<<<blocks, threads>>>(hidden, cell, W_ih2, W_hh2, b_ih2, b_hh2, W_out, b_out, out);
}

// round 6
// speedup vs baseline: 2.8201x; 1.0062x over previous
#include <cuda_runtime.h>
#include <cuda_fp16.h>

// LinearNavigator, two-pass, 2 elements/thread packed in __half2.
// R6: each gate dot-product split into 4 independent HFMA2 chains (ILP 4)
// with __hadd2 combine tree; weights streamed as uint4 (no staging arrays).
// out layout: out[B,5], h_stack[2,B,20], c_stack[2,B,20]

#define NB 1048576
#define HDIM 20
#define HBASE ((size_t)5 * NB)
#define CBASE ((size_t)5 * NB + (size_t)2 * NB * HDIM)

__device__ __forceinline__ float sigmoid_(float x) {
    return __fdividef(1.0f, 1.0f + __expf(-x));
}
__device__ __forceinline__ float tanh_(float x) {
    float e = __expf(2.0f * x);
    return 1.0f - __fdividef(2.0f, e + 1.0f);
}
__device__ __forceinline__ __half2 H2(unsigned u) {
    __half2 h; *reinterpret_cast<unsigned*>(&h) = u; return h;
}

// ---------------------------------------------------------------------------
// Pass 1: preproc + LSTM layer 1. Writes h_stack[0], c_stack[0].
// ---------------------------------------------------------------------------
__global__ __launch_bounds__(128)
void navi_l1(const float* __restrict__ inp, const float* __restrict__ hidden,
             const float* __restrict__ cell,
             const float* __restrict__ W_ih1, const float* __restrict__ W_hh1,
             const float* __restrict__ b_ih1, const float* __restrict__ b_hh1,
             float* __restrict__ out)
{
    __shared__ __align__(16) __half2 sW[80 * HDIM];  // Whh1 splat (w,w)
    __shared__ float sWih[160];                      // Wih1 fp32
    __shared__ float sb[80];

    const int t = threadIdx.x;
    for (int i = t; i < 1600; i += 128) sW[i] = __float2half2_rn(W_hh1[i]);
    for (int i = t; i < 160;  i += 128) sWih[i] = W_ih1[i];
    for (int i = t; i < 80;   i += 128) sb[i] = b_ih1[i] + b_hh1[i];
    __syncthreads();

    const size_t b0 = ((size_t)blockIdx.x * 128 + t) * 2;

    // preproc (fp32)
    const float THR = 4.5399929762484854e-05f;  // exp(-10)
    const float E10 = 22026.465794806718f;      // exp(10)
    float x0a, x1a, x0b, x1b;
    {
        float v = inp[b0];
        float av = fabsf(v);
        if (av >= THR) { x0a = __logf(av + 1e-8f) * 0.1f; x1a = (v > 0.0f) ? 1.0f : -1.0f; }
        else           { x0a = -1.0f; x1a = E10 * v; }
        v = inp[b0 + 1];
        av = fabsf(v);
        if (av >= THR) { x0b = __logf(av + 1e-8f) * 0.1f; x1b = (v > 0.0f) ? 1.0f : -1.0f; }
        else           { x0b = -1.0f; x1b = E10 * v; }
    }

    __half2 hp[HDIM];
    {
        const float4* hA = reinterpret_cast<const float4*>(hidden + b0 * HDIM);
        #pragma unroll
        for (int q = 0; q < 5; q++) {
            float4 A = hA[q], Bv = hA[q + 5];
            hp[4*q+0] = __floats2half2_rn(A.x, Bv.x);
            hp[4*q+1] = __floats2half2_rn(A.y, Bv.y);
            hp[4*q+2] = __floats2half2_rn(A.z, Bv.z);
            hp[4*q+3] = __floats2half2_rn(A.w, Bv.w);
        }
    }

    const float4* cIn = reinterpret_cast<const float4*>(cell + b0 * HDIM);
    float4* hOut = reinterpret_cast<float4*>(out + HBASE + b0 * HDIM);
    float4* cOut = reinterpret_cast<float4*>(out + CBASE + b0 * HDIM);

    #pragma unroll 1
    for (int jj = 0; jj < 5; jj++) {
        float4 cA = cIn[jj], cB = cIn[jj + 5];
        float4 hnA, hnB, cnA, cnB;
        float* cAv = (float*)&cA;  float* cBv = (float*)&cB;
        float* hnAv = (float*)&hnA; float* hnBv = (float*)&hnB;
        float* cnAv = (float*)&cnA; float* cnBv = (float*)&cnB;
        #pragma unroll
        for (int j2 = 0; j2 < 4; j2++) {
            const int j = jj * 4 + j2;
            float gAv[4], gBv[4];
            #pragma unroll
            for (int g = 0; g < 4; g++) {
                const int r = g * 20 + j;
                const uint4* W = reinterpret_cast<const uint4*>(sW + r * HDIM);
                uint4 q0 = W[0], q1 = W[1], q2 = W[2], q3 = W[3], q4 = W[4];
                // 4 independent chains of 5
                __half2 a0 = __hmul2(H2(q0.x), hp[0]);
                __half2 a1 = __hmul2(H2(q1.y), hp[5]);
                __half2 a2 = __hmul2(H2(q2.z), hp[10]);
                __half2 a3 = __hmul2(H2(q3.w), hp[15]);
                a0 = __hfma2(H2(q0.y), hp[1],  a0);
                a1 = __hfma2(H2(q1.z), hp[6],  a1);
                a2 = __hfma2(H2(q2.w), hp[11], a2);
                a3 = __hfma2(H2(q4.x), hp[16], a3);
                a0 = __hfma2(H2(q0.z), hp[2],  a0);
                a1 = __hfma2(H2(q1.w), hp[7],  a1);
                a2 = __hfma2(H2(q3.x), hp[12], a2);
                a3 = __hfma2(H2(q4.y), hp[17], a3);
                a0 = __hfma2(H2(q0.w), hp[3],  a0);
                a1 = __hfma2(H2(q2.x), hp[8],  a1);
                a2 = __hfma2(H2(q3.y), hp[13], a2);
                a3 = __hfma2(H2(q4.z), hp[18], a3);
                a0 = __hfma2(H2(q1.x), hp[4],  a0);
                a1 = __hfma2(H2(q2.y), hp[9],  a1);
                a2 = __hfma2(H2(q3.z), hp[14], a2);
                a3 = __hfma2(H2(q4.w), hp[19], a3);
                __half2 s = __hadd2(__hadd2(a0, a1), __hadd2(a2, a3));
                float2 p = __half22float2(s);
                const float bb = sb[r];
                const float wa = sWih[r * 2], wb = sWih[r * 2 + 1];
                gAv[g] = bb + p.x + x0a * wa + x1a * wb;
                gBv[g] = bb + p.y + x0b * wa + x1b * wb;
            }
            // gates: 0=i 1=f 2=g 3=o
            float cn = sigmoid_(gAv[1]) * cAv[j2] + sigmoid_(gAv[0]) * tanh_(gAv[2]);
            cnAv[j2] = cn;
            hnAv[j2] = sigmoid_(gAv[3]) * tanh_(cn);
            cn = sigmoid_(gBv[1]) * cBv[j2] + sigmoid_(gBv[0]) * tanh_(gBv[2]);
            cnBv[j2] = cn;
            hnBv[j2] = sigmoid_(gBv[3]) * tanh_(cn);
        }
        hOut[jj] = hnA; hOut[jj + 5] = hnB;
        cOut[jj] = cnA; cOut[jj + 5] = cnB;
    }
}

// ---------------------------------------------------------------------------
// Pass 2: LSTM layer 2 + head. Reads hn1 from out (h_stack[0]).
// ---------------------------------------------------------------------------
__global__ __launch_bounds__(128)
void navi_l2(const float* __restrict__ hidden, const float* __restrict__ cell,
             const float* __restrict__ W_ih2, const float* __restrict__ W_hh2,
             const float* __restrict__ b_ih2, const float* __restrict__ b_hh2,
             const float* __restrict__ W_out, const float* __restrict__ b_out,
             float* __restrict__ out)
{
    __shared__ __align__(16) __half2 sWx[80 * HDIM];
    __shared__ __align__(16) __half2 sWh[80 * HDIM];
    __shared__ float sb[80];
    __shared__ float sWo[HDIM];
    __shared__ float sbo;

    const int t = threadIdx.x;
    for (int i = t; i < 1600; i += 128) sWx[i] = __float2half2_rn(W_ih2[i]);
    for (int i = t; i < 1600; i += 128) sWh[i] = __float2half2_rn(W_hh2[i]);
    for (int i = t; i < 80;   i += 128) sb[i] = b_ih2[i] + b_hh2[i];
    for (int i = t; i < HDIM; i += 128) sWo[i] = W_out[i];
    if (t == 0) sbo = b_out[0];
    __syncthreads();

    const size_t b0 = ((size_t)blockIdx.x * 128 + t) * 2;

    __half2 xp[HDIM], hp[HDIM];
    {
        const float4* xA = reinterpret_cast<const float4*>(out + HBASE + b0 * HDIM);
        const float4* hA = reinterpret_cast<const float4*>(hidden + (size_t)NB * HDIM + b0 * HDIM);
        #pragma unroll
        for (int q = 0; q < 5; q++) {
            float4 A = xA[q], Bv = xA[q + 5];
            xp[4*q+0] = __floats2half2_rn(A.x, Bv.x);
            xp[4*q+1] = __floats2half2_rn(A.y, Bv.y);
            xp[4*q+2] = __floats2half2_rn(A.z, Bv.z);
            xp[4*q+3] = __floats2half2_rn(A.w, Bv.w);
            A = hA[q]; Bv = hA[q + 5];
            hp[4*q+0] = __floats2half2_rn(A.x, Bv.x);
            hp[4*q+1] = __floats2half2_rn(A.y, Bv.y);
            hp[4*q+2] = __floats2half2_rn(A.z, Bv.z);
            hp[4*q+3] = __floats2half2_rn(A.w, Bv.w);
        }
    }

    const float4* cIn = reinterpret_cast<const float4*>(cell + (size_t)NB * HDIM + b0 * HDIM);
    float4* hOut = reinterpret_cast<float4*>(out + HBASE + (size_t)NB * HDIM + b0 * HDIM);
    float4* cOut = reinterpret_cast<float4*>(out + CBASE + (size_t)NB * HDIM + b0 * HDIM);

    float oA = sbo, oB = sbo;

    #pragma unroll 1
    for (int jj = 0; jj < 5; jj++) {
        float4 cA = cIn[jj], cB = cIn[jj + 5];
        float4 hnA, hnB, cnA, cnB;
        float* cAv = (float*)&cA;  float* cBv = (float*)&cB;
        float* hnAv = (float*)&hnA; float* hnBv = (float*)&hnB;
        float* cnAv = (float*)&cnA; float* cnBv = (float*)&cnB;
        #pragma unroll
        for (int j2 = 0; j2 < 4; j2++) {
            const int j = jj * 4 + j2;
            float gAv[4], gBv[4];
            #pragma unroll
            for (int g = 0; g < 4; g++) {
                const int r = g * 20 + j;
                const uint4* Wx = reinterpret_cast<const uint4*>(sWx + r * HDIM);
                const uint4* Wh = reinterpret_cast<const uint4*>(sWh + r * HDIM);
                uint4 x0 = Wx[0], x1 = Wx[1], x2 = Wx[2], x3 = Wx[3], x4 = Wx[4];
                uint4 h0 = Wh[0], h1 = Wh[1], h2 = Wh[2], h3 = Wh[3], h4 = Wh[4];
                // 4 independent chains of 10: 2 over x, 2 over h
                __half2 a0 = __hmul2(H2(x0.x), xp[0]);
                __half2 a1 = __hmul2(H2(x2.z), xp[10]);
                __half2 a2 = __hmul2(H2(h0.x), hp[0]);
                __half2 a3 = __hmul2(H2(h2.z), hp[10]);
                a0 = __hfma2(H2(x0.y), xp[1],  a0);
                a1 = __hfma2(H2(x2.w), xp[11], a1);
                a2 = __hfma2(H2(h0.y), hp[1],  a2);
                a3 = __hfma2(H2(h2.w), hp[11], a3);
                a0 = __hfma2(H2(x0.z), xp[2],  a0);
                a1 = __hfma2(H2(x3.x), xp[12], a1);
                a2 = __hfma2(H2(h0.z), hp[2],  a2);
                a3 = __hfma2(H2(h3.x), hp[12], a3);
                a0 = __hfma2(H2(x0.w), xp[3],  a0);
                a1 = __hfma2(H2(x3.y), xp[13], a1);
                a2 = __hfma2(H2(h0.w), hp[3],  a2);
                a3 = __hfma2(H2(h3.y), hp[13], a3);
                a0 = __hfma2(H2(x1.x), xp[4],  a0);
                a1 = __hfma2(H2(x3.z), xp[14], a1);
                a2 = __hfma2(H2(h1.x), hp[4],  a2);
                a3 = __hfma2(H2(h3.z), hp[14], a3);
                a0 = __hfma2(H2(x1.y), xp[5],  a0);
                a1 = __hfma2(H2(x3.w), xp[15], a1);
                a2 = __hfma2(H2(h1.y), hp[5],  a2);
                a3 = __hfma2(H2(h3.w), hp[15], a3);
                a0 = __hfma2(H2(x1.z), xp[6],  a0);
                a1 = __hfma2(H2(x4.x), xp[16], a1);
                a2 = __hfma2(H2(h1.z), hp[6],  a2);
                a3 = __hfma2(H2(h4.x), hp[16], a3);
                a0 = __hfma2(H2(x1.w), xp[7],  a0);
                a1 = __hfma2(H2(x4.y), xp[17], a1);
                a2 = __hfma2(H2(h1.w), hp[7],  a2);
                a3 = __hfma2(H2(h4.y), hp[17], a3);
                a0 = __hfma2(H2(x2.x), xp[8],  a0);
                a1 = __hfma2(H2(x4.z), xp[18], a1);
                a2 = __hfma2(H2(h2.x), hp[8],  a2);
                a3 = __hfma2(H2(h4.z), hp[18], a3);
                a0 = __hfma2(H2(x2.y), xp[9],  a0);
                a1 = __hfma2(H2(x4.w), xp[19], a1);
                a2 = __hfma2(H2(h2.y), hp[9],  a2);
                a3 = __hfma2(H2(h4.w), hp[19], a3);
                __half2 s = __hadd2(__hadd2(a0, a1), __hadd2(a2, a3));
                float2 p = __half22float2(s);
                const float bb = sb[r];
                gAv[g] = bb + p.x;
                gBv[g] = bb + p.y;
            }
            float cn = sigmoid_(gAv[1]) * cAv[j2] + sigmoid_(gAv[0]) * tanh_(gAv[2]);
            cnAv[j2] = cn;
            float hn = sigmoid_(gAv[3]) * tanh_(cn);
            hnAv[j2] = hn;
            oA += hn * sWo[j];
            cn = sigmoid_(gBv[1]) * cBv[j2] + sigmoid_(gBv[0]) * tanh_(gBv[2]);
            cnBv[j2] = cn;
            hn = sigmoid_(gBv[3]) * tanh_(cn);
            hnBv[j2] = hn;
            oB += hn * sWo[j];
        }
        hOut[jj] = hnA; hOut[jj + 5] = hnB;
        cOut[jj] = cnA; cOut[jj + 5] = cnB;
    }

    float* o5 = out + b0 * 5;
    #pragma unroll
    for (int s = 0; s < 5; s++) {
        o5[s]     = oA * (float)(s + 1);
        o5[s + 5] = oB * (float)(s + 1);
    }
}

extern "C" void kernel_launch(void* const* d_in, const int* in_sizes, int n_in,
                              void* d_out, int out_size) {
    const float* inp    = (const float*)d_in[0];
    const float* hidden = (const float*)d_in[1];
    const float* cell   = (const float*)d_in[2];
    const float* W_ih1  = (const float*)d_in[3];
    const float* W_hh1  = (const float*)d_in[4];
    const float* b_ih1  = (const float*)d_in[5];
    const float* b_hh1  = (const float*)d_in[6];
    const float* W_ih2  = (const float*)d_in[7];
    const float* W_hh2  = (const float*)d_in[8];
    const float* b_ih2  = (const float*)d_in[9];
    const float* b_hh2  = (const float*)d_in[10];
    const float* W_out  = (const float*)d_in[11];
    const float* b_out  = (const float*)d_in[12];
    float* out = (float*)d_out;

    const int threads = 128;
    const int blocks = NB / (threads * 2);  // 2 elements per thread
    navi_l1<<<blocks, threads>>>(inp, hidden, cell, W_ih1, W_hh1, b_ih1, b_hh1, out);
    navi_l2<<<blocks, threads>>>(hidden, cell, W_ih2, W_hh2, b_ih2, b_hh2, W_out, b_out, out);
}

// round 10
// speedup vs baseline: 3.2876x; 1.1658x over previous
#include <cuda_runtime.h>
#include <cuda_fp16.h>
#include <cstdint>

// LinearNavigator via warp-level HMMA (mma.sync m16n8k16, f16 in / f32 accum).
// gates[128-elem tile, 80] = A[*,K] x B[K,80], B rows permuted n=4j+gate.
// Two chained layers per warp (K=32, K=48), smem-staged coalesced IO.
// R10: __align__(16) on all shared arrays accessed through wider types.
// out layout: out[B,5], h_stack[2,B,20], c_stack[2,B,20]

#define NB 1048576
#define HDIM 20
#define HBASE ((size_t)5 * NB)
#define CBASE (HBASE + (size_t)2 * NB * HDIM)

__device__ __forceinline__ float sigm_(float x) {
    return __fdividef(1.0f, 1.0f + __expf(-x));
}
__device__ __forceinline__ float tanh_(float x) {
    float e = __expf(2.0f * x);
    return 1.0f - __fdividef(2.0f, e + 1.0f);
}

__device__ __forceinline__ void mma16816(float& d0, float& d1, float& d2, float& d3,
                                         uint32_t a0, uint32_t a1, uint32_t a2, uint32_t a3,
                                         uint32_t b0, uint32_t b1) {
    asm volatile(
        "mma.sync.aligned.m16n8k16.row.col.f32.f16.f16.f32 "
        "{%0,%1,%2,%3}, {%4,%5,%6,%7}, {%8,%9}, {%0,%1,%2,%3};"
        : "+f"(d0), "+f"(d1), "+f"(d2), "+f"(d3)
        : "r"(a0), "r"(a1), "r"(a2), "r"(a3), "r"(b0), "r"(b1));
}

__global__ __launch_bounds__(128)
void navi_mma(const float* __restrict__ inp, const float* __restrict__ hidden,
              const float* __restrict__ cell,
              const float* __restrict__ W_ih1, const float* __restrict__ W_hh1,
              const float* __restrict__ b_ih1, const float* __restrict__ b_hh1,
              const float* __restrict__ W_ih2, const float* __restrict__ W_hh2,
              const float* __restrict__ b_ih2, const float* __restrict__ b_hh2,
              const float* __restrict__ W_out, const float* __restrict__ b_out,
              float* __restrict__ out)
{
    // Weights: B1 [n=80][k=32], B2 [n=80][k=48], n = 4j + gate, row r = gate*20+j
    __shared__ __align__(16) __half B1s[80][32];
    __shared__ __align__(16) __half B2s[80][48];
    __shared__ float  Wos[20];
    __shared__ float  bos;
    // per-warp stages (16 rows = one m-tile)
    __shared__ __align__(16) __half A1s[4][16][32];
    __shared__ __align__(16) __half A2s[4][16][48];
    __shared__ __align__(16) float  Cst[4][16][20];
    __shared__ __align__(16) float  Hst[4][16][20];

    const int t = threadIdx.x;
    const int w = t >> 5;
    const int lane = t & 31;
    const int g = lane >> 2;          // group (row within m-tile: g and g+8)
    const int tig = lane & 3;         // thread-in-group (col pair selector)
    const bool oddl = (tig & 1);

    // unified activation constants: even -> sigmoid, odd -> tanh
    const float As = oddl ? 2.0f : -1.0f;
    const float Aa = oddl ? 1.0f : 0.0f;
    const float Ab = oddl ? -2.0f : 1.0f;

    // ---------------- one-time weight fill ----------------
    {
        __half2* z1 = (__half2*)&B1s[0][0];
        for (int i = t; i < 80 * 16; i += 128) z1[i] = __floats2half2_rn(0.f, 0.f);
        __half2* z2 = (__half2*)&B2s[0][0];
        for (int i = t; i < 80 * 24; i += 128) z2[i] = __floats2half2_rn(0.f, 0.f);
    }
    __syncthreads();
    for (int i = t; i < 1600; i += 128) {
        int r = i / 20, k = i % 20;
        int n = 4 * (r % 20) + (r / 20);
        B1s[n][2 + k] = __float2half_rn(W_hh1[i]);
        B2s[n][k]      = __float2half_rn(W_ih2[i]);
        B2s[n][20 + k] = __float2half_rn(W_hh2[i]);
    }
    for (int i = t; i < 160; i += 128) {
        int r = i / 2, k = i % 2;
        int n = 4 * (r % 20) + (r / 20);
        B1s[n][k] = __float2half_rn(W_ih1[i]);
    }
    for (int i = t; i < 80; i += 128) {
        int n = 4 * (i % 20) + (i / 20);
        B1s[n][22] = __float2half_rn(b_ih1[i] + b_hh1[i]);
        B2s[n][40] = __float2half_rn(b_ih2[i] + b_hh2[i]);
    }
    if (t < 20) Wos[t] = W_out[t];
    if (t == 20) bos = b_out[0];
    __syncthreads();

    // ---------------- tile loop: 4 tiles of 128 elements per block ----------------
    #pragma unroll 1
    for (int it = 0; it < 4; ++it) {
        const size_t tileBase = ((size_t)blockIdx.x * 4 + it) * 128;

        #pragma unroll 1
        for (int mt = 0; mt < 2; ++mt) {
            const size_t base = tileBase + (size_t)w * 32 + mt * 16;  // 16 elements

            // ---- phase A: preproc + A1 fill + c0 stage (lanes 0..15) ----
            if (lane < 16) {
                const size_t e = base + lane;
                const float v = inp[e];
                const float av = fabsf(v);
                float x0, x1;
                if (av >= 4.5399929762484854e-05f) {
                    x0 = __logf(av + 1e-8f) * 0.1f;
                    x1 = (v > 0.0f) ? 1.0f : -1.0f;
                } else {
                    x0 = -1.0f;
                    x1 = 22026.465794806718f * v;
                }
                const float4* hq = (const float4*)(hidden + e * HDIM);
                float4 h0 = hq[0], h1 = hq[1], h2 = hq[2], h3 = hq[3], h4 = hq[4];
                __half2* Ar = (__half2*)&A1s[w][lane][0];
                Ar[0]  = __floats2half2_rn(x0, x1);
                Ar[1]  = __floats2half2_rn(h0.x, h0.y);
                Ar[2]  = __floats2half2_rn(h0.z, h0.w);
                Ar[3]  = __floats2half2_rn(h1.x, h1.y);
                Ar[4]  = __floats2half2_rn(h1.z, h1.w);
                Ar[5]  = __floats2half2_rn(h2.x, h2.y);
                Ar[6]  = __floats2half2_rn(h2.z, h2.w);
                Ar[7]  = __floats2half2_rn(h3.x, h3.y);
                Ar[8]  = __floats2half2_rn(h3.z, h3.w);
                Ar[9]  = __floats2half2_rn(h4.x, h4.y);
                Ar[10] = __floats2half2_rn(h4.z, h4.w);
                Ar[11] = __floats2half2_rn(1.0f, 0.0f);   // bias col 22
                Ar[12] = __floats2half2_rn(0.f, 0.f);
                Ar[13] = __floats2half2_rn(0.f, 0.f);
                Ar[14] = __floats2half2_rn(0.f, 0.f);
                Ar[15] = __floats2half2_rn(0.f, 0.f);
                const float4* cq = (const float4*)(cell + e * HDIM);
                float4* Cr = (float4*)&Cst[w][lane][0];
                Cr[0] = cq[0]; Cr[1] = cq[1]; Cr[2] = cq[2]; Cr[3] = cq[3]; Cr[4] = cq[4];
            }
            __syncwarp();

            // ---- layer 1: A fragments (K=32, 2 slices) ----
            uint32_t a1f[2][4];
            #pragma unroll
            for (int s = 0; s < 2; ++s) {
                a1f[s][0] = *(const uint32_t*)&A1s[w][g][16*s + 2*tig];
                a1f[s][1] = *(const uint32_t*)&A1s[w][g+8][16*s + 2*tig];
                a1f[s][2] = *(const uint32_t*)&A1s[w][g][16*s + 2*tig + 8];
                a1f[s][3] = *(const uint32_t*)&A1s[w][g+8][16*s + 2*tig + 8];
            }

            #pragma unroll 1
            for (int nt = 0; nt < 10; ++nt) {
                float d0 = 0.f, d1 = 0.f, d2 = 0.f, d3 = 0.f;
                #pragma unroll
                for (int s = 0; s < 2; ++s) {
                    uint32_t b0 = *(const uint32_t*)&B1s[8*nt + g][16*s + 2*tig];
                    uint32_t b1 = *(const uint32_t*)&B1s[8*nt + g][16*s + 2*tig + 8];
                    mma16816(d0, d1, d2, d3, a1f[s][0], a1f[s][1], a1f[s][2], a1f[s][3], b0, b1);
                }
                // epilogue: lane pair (tig even: i,f) / (tig odd: g,o); j = 2nt + (tig>>1)
                const int j = 2*nt + (tig >> 1);
                float e0 = Aa + __fdividef(Ab, __expf(As * d0) + 1.0f);  // even: sig(i); odd: tanh(g)
                float e1 = sigm_(d1);                                     // sig(f) / sig(o)
                float e2 = Aa + __fdividef(Ab, __expf(As * d2) + 1.0f);
                float e3 = sigm_(d3);
                float xg0 = __shfl_xor_sync(0xffffffffu, e0, 1);
                float xg8 = __shfl_xor_sync(0xffffffffu, e2, 1);
                float cn0 = 0.f, cn8 = 0.f;
                if (!oddl) {
                    float co0 = Cst[w][g][j], co8 = Cst[w][g+8][j];
                    cn0 = e1 * co0 + e0 * xg0;
                    cn8 = e3 * co8 + e2 * xg8;
                    Cst[w][g][j] = cn0; Cst[w][g+8][j] = cn8;
                }
                float cn8x = __shfl_xor_sync(0xffffffffu, cn8, 1);
                float tc = tanh_(oddl ? cn8x : cn0);
                float tcx = __shfl_xor_sync(0xffffffffu, tc, 1);
                if (oddl) {
                    float h0v = e1 * tcx;   // row g
                    float h8v = e3 * tc;    // row g+8
                    Hst[w][g][j] = h0v;  Hst[w][g+8][j] = h8v;
                    A2s[w][g][j]   = __float2half_rn(h0v);
                    A2s[w][g+8][j] = __float2half_rn(h8v);
                }
            }
            __syncwarp();

            // ---- store h_stack[0]/c_stack[0]; then refill stages for layer 2 ----
            for (int idx = lane; idx < 80; idx += 32) {
                int row = idx / 5, q = idx % 5;
                size_t e = base + row;
                *(float4*)&out[HBASE + e * HDIM + 4*q] = *(const float4*)&Hst[w][row][4*q];
                *(float4*)&out[CBASE + e * HDIM + 4*q] = *(const float4*)&Cst[w][row][4*q];
            }
            __syncwarp();
            for (int idx = lane; idx < 80; idx += 32) {
                int row = idx / 5, q = idx % 5;
                size_t e = base + row;
                float4 c1q = *(const float4*)&cell[(size_t)NB * HDIM + e * HDIM + 4*q];
                *(float4*)&Cst[w][row][4*q] = c1q;
                float4 h1q = *(const float4*)&hidden[(size_t)NB * HDIM + e * HDIM + 4*q];
                *(__half2*)&A2s[w][row][20 + 4*q]     = __floats2half2_rn(h1q.x, h1q.y);
                *(__half2*)&A2s[w][row][20 + 4*q + 2] = __floats2half2_rn(h1q.z, h1q.w);
            }
            if (lane < 16) {
                __half2* Ar = (__half2*)&A2s[w][lane][40];
                Ar[0] = __floats2half2_rn(1.0f, 0.0f);   // bias col 40
                Ar[1] = __floats2half2_rn(0.f, 0.f);
                Ar[2] = __floats2half2_rn(0.f, 0.f);
                Ar[3] = __floats2half2_rn(0.f, 0.f);
            }
            __syncwarp();

            // ---- layer 2: A fragments (K=48, 3 slices) ----
            uint32_t a2f[3][4];
            #pragma unroll
            for (int s = 0; s < 3; ++s) {
                a2f[s][0] = *(const uint32_t*)&A2s[w][g][16*s + 2*tig];
                a2f[s][1] = *(const uint32_t*)&A2s[w][g+8][16*s + 2*tig];
                a2f[s][2] = *(const uint32_t*)&A2s[w][g][16*s + 2*tig + 8];
                a2f[s][3] = *(const uint32_t*)&A2s[w][g+8][16*s + 2*tig + 8];
            }

            float o_lo = 0.f, o_hi = 0.f;
            #pragma unroll 1
            for (int nt = 0; nt < 10; ++nt) {
                float d0 = 0.f, d1 = 0.f, d2 = 0.f, d3 = 0.f;
                #pragma unroll
                for (int s = 0; s < 3; ++s) {
                    uint32_t b0 = *(const uint32_t*)&B2s[8*nt + g][16*s + 2*tig];
                    uint32_t b1 = *(const uint32_t*)&B2s[8*nt + g][16*s + 2*tig + 8];
                    mma16816(d0, d1, d2, d3, a2f[s][0], a2f[s][1], a2f[s][2], a2f[s][3], b0, b1);
                }
                const int j = 2*nt + (tig >> 1);
                float e0 = Aa + __fdividef(Ab, __expf(As * d0) + 1.0f);
                float e1 = sigm_(d1);
                float e2 = Aa + __fdividef(Ab, __expf(As * d2) + 1.0f);
                float e3 = sigm_(d3);
                float xg0 = __shfl_xor_sync(0xffffffffu, e0, 1);
                float xg8 = __shfl_xor_sync(0xffffffffu, e2, 1);
                float cn0 = 0.f, cn8 = 0.f;
                if (!oddl) {
                    float co0 = Cst[w][g][j], co8 = Cst[w][g+8][j];
                    cn0 = e1 * co0 + e0 * xg0;
                    cn8 = e3 * co8 + e2 * xg8;
                    Cst[w][g][j] = cn0; Cst[w][g+8][j] = cn8;
                }
                float cn8x = __shfl_xor_sync(0xffffffffu, cn8, 1);
                float tc = tanh_(oddl ? cn8x : cn0);
                float tcx = __shfl_xor_sync(0xffffffffu, tc, 1);
                if (oddl) {
                    float h0v = e1 * tcx;
                    float h8v = e3 * tc;
                    Hst[w][g][j] = h0v;  Hst[w][g+8][j] = h8v;
                    float wo = Wos[j];
                    o_lo += h0v * wo;
                    o_hi += h8v * wo;
                }
            }
            __syncwarp();

            // ---- store h_stack[1]/c_stack[1] ----
            for (int idx = lane; idx < 80; idx += 32) {
                int row = idx / 5, q = idx % 5;
                size_t e = base + row;
                *(float4*)&out[HBASE + (size_t)NB * HDIM + e * HDIM + 4*q] = *(const float4*)&Hst[w][row][4*q];
                *(float4*)&out[CBASE + (size_t)NB * HDIM + e * HDIM + 4*q] = *(const float4*)&Cst[w][row][4*q];
            }

            // ---- head: combine odd-lane partials (tig1: even j, tig3: odd j) ----
            float s_lo = o_lo + __shfl_xor_sync(0xffffffffu, o_lo, 2);
            float s_hi = o_hi + __shfl_xor_sync(0xffffffffu, o_hi, 2);
            if (tig == 1) {
                size_t e = base + g;
                float o = bos + s_lo;
                float* o5 = out + e * 5;
                #pragma unroll
                for (int s = 0; s < 5; ++s) o5[s] = o * (float)(s + 1);
            }
            if (tig == 3) {
                size_t e = base + g + 8;
                float o = bos + s_hi;
                float* o5 = out + e * 5;
                #pragma unroll
                for (int s = 0; s < 5; ++s) o5[s] = o * (float)(s + 1);
            }
            __syncwarp();
        }
    }
}

extern "C" void kernel_launch(void* const* d_in, const int* in_sizes, int n_in,
                              void* d_out, int out_size) {
    const float* inp    = (const float*)d_in[0];
    const float* hidden = (const float*)d_in[1];
    const float* cell   = (const float*)d_in[2];
    const float* W_ih1  = (const float*)d_in[3];
    const float* W_hh1  = (const float*)d_in[4];
    const float* b_ih1  = (const float*)d_in[5];
    const float* b_hh1  = (const float*)d_in[6];
    const float* W_ih2  = (const float*)d_in[7];
    const float* W_hh2  = (const float*)d_in[8];
    const float* b_ih2  = (const float*)d_in[9];
    const float* b_hh2  = (const float*)d_in[10];
    const float* W_out  = (const float*)d_in[11];
    const float* b_out  = (const float*)d_in[12];
    float* out = (float*)d_out;

    // 2048 blocks x 128 threads; each block: 4 tiles of 128 elements
    navi_mma<<<2048, 128>>>(inp, hidden, cell,
                            W_ih1, W_hh1, b_ih1, b_hh1,
                            W_ih2, W_hh2, b_ih2, b_hh2,
                            W_out, b_out, out);
}

// round 12
// speedup vs baseline: 4.0657x; 1.2367x over previous
#include <cuda_runtime.h>
#include <cuda_fp16.h>
#include <cstdint>

// LinearNavigator via warp-level HMMA (mma.sync m16n8k16, f16 in / f32 accum).
// R12: R11 (conflict-free padding + 2-shuffle epilogue) with the odd-lane
// gate-selection fix: odd lanes own row g+8 -> their (g,o) gates are d2,d3.
// out layout: out[B,5], h_stack[2,B,20], c_stack[2,B,20]

#define NB 1048576
#define HDIM 20
#define HBASE ((size_t)5 * NB)
#define CBASE (HBASE + (size_t)2 * NB * HDIM)

__device__ __forceinline__ float sigm_(float x) {
    return __fdividef(1.0f, 1.0f + __expf(-x));
}
__device__ __forceinline__ float tanh_(float x) {
    float e = __expf(2.0f * x);
    return 1.0f - __fdividef(2.0f, e + 1.0f);
}

__device__ __forceinline__ void mma16816(float& d0, float& d1, float& d2, float& d3,
                                         uint32_t a0, uint32_t a1, uint32_t a2, uint32_t a3,
                                         uint32_t b0, uint32_t b1) {
    asm volatile(
        "mma.sync.aligned.m16n8k16.row.col.f32.f16.f16.f32 "
        "{%0,%1,%2,%3}, {%4,%5,%6,%7}, {%8,%9}, {%0,%1,%2,%3};"
        : "+f"(d0), "+f"(d1), "+f"(d2), "+f"(d3)
        : "r"(a0), "r"(a1), "r"(a2), "r"(a3), "r"(b0), "r"(b1));
}

__global__ __launch_bounds__(128)
void navi_mma(const float* __restrict__ inp, const float* __restrict__ hidden,
              const float* __restrict__ cell,
              const float* __restrict__ W_ih1, const float* __restrict__ W_hh1,
              const float* __restrict__ b_ih1, const float* __restrict__ b_hh1,
              const float* __restrict__ W_ih2, const float* __restrict__ W_hh2,
              const float* __restrict__ b_ih2, const float* __restrict__ b_hh2,
              const float* __restrict__ W_out, const float* __restrict__ b_out,
              float* __restrict__ out)
{
    // Weights (padded rows for conflict-free fragment loads):
    // B1 [n=80][k pad 40], B2 [n=80][k pad 56]; n = 4j + gate, weight row r = gate*20+j
    __shared__ __align__(16) __half B1s[80][40];
    __shared__ __align__(16) __half B2s[80][56];
    __shared__ float  Wos[20];
    __shared__ float  bos;
    // per-warp stages (16 rows = one m-tile), padded
    __shared__ __align__(16) __half A1s[4][16][40];
    __shared__ __align__(16) __half A2s[4][16][56];
    __shared__ __align__(16) float  Cst[4][16][20];
    __shared__ __align__(16) float  Hst[4][16][20];

    const int t = threadIdx.x;
    const int w = t >> 5;
    const int lane = t & 31;
    const int g = lane >> 2;          // row group: rows g and g+8
    const int tig = lane & 3;
    const bool oddl = (tig & 1);
    const int myrow = oddl ? g + 8 : g;

    // ---------------- one-time weight fill ----------------
    {
        __half2* z1 = (__half2*)&B1s[0][0];
        for (int i = t; i < 80 * 20; i += 128) z1[i] = __floats2half2_rn(0.f, 0.f);
        __half2* z2 = (__half2*)&B2s[0][0];
        for (int i = t; i < 80 * 28; i += 128) z2[i] = __floats2half2_rn(0.f, 0.f);
    }
    __syncthreads();
    for (int i = t; i < 1600; i += 128) {
        int r = i / 20, k = i % 20;
        int n = 4 * (r % 20) + (r / 20);
        B1s[n][2 + k] = __float2half_rn(W_hh1[i]);
        B2s[n][k]      = __float2half_rn(W_ih2[i]);
        B2s[n][20 + k] = __float2half_rn(W_hh2[i]);
    }
    for (int i = t; i < 160; i += 128) {
        int r = i / 2, k = i % 2;
        int n = 4 * (r % 20) + (r / 20);
        B1s[n][k] = __float2half_rn(W_ih1[i]);
    }
    for (int i = t; i < 80; i += 128) {
        int n = 4 * (i % 20) + (i / 20);
        B1s[n][22] = __float2half_rn(b_ih1[i] + b_hh1[i]);
        B2s[n][40] = __float2half_rn(b_ih2[i] + b_hh2[i]);
    }
    if (t < 20) Wos[t] = W_out[t];
    if (t == 20) bos = b_out[0];
    __syncthreads();

    // ---------------- tile loop: 4 tiles of 128 elements per block ----------------
    #pragma unroll 1
    for (int it = 0; it < 4; ++it) {
        const size_t tileBase = ((size_t)blockIdx.x * 4 + it) * 128;

        #pragma unroll 1
        for (int mt = 0; mt < 2; ++mt) {
            const size_t base = tileBase + (size_t)w * 32 + mt * 16;  // 16 elements

            // ---- phase A: preproc + A1 fill + c0 stage (lanes 0..15) ----
            if (lane < 16) {
                const size_t e = base + lane;
                const float v = inp[e];
                const float av = fabsf(v);
                float x0, x1;
                if (av >= 4.5399929762484854e-05f) {
                    x0 = __logf(av + 1e-8f) * 0.1f;
                    x1 = (v > 0.0f) ? 1.0f : -1.0f;
                } else {
                    x0 = -1.0f;
                    x1 = 22026.465794806718f * v;
                }
                const float4* hq = (const float4*)(hidden + e * HDIM);
                float4 h0 = hq[0], h1 = hq[1], h2 = hq[2], h3 = hq[3], h4 = hq[4];
                __half2* Ar = (__half2*)&A1s[w][lane][0];
                Ar[0]  = __floats2half2_rn(x0, x1);
                Ar[1]  = __floats2half2_rn(h0.x, h0.y);
                Ar[2]  = __floats2half2_rn(h0.z, h0.w);
                Ar[3]  = __floats2half2_rn(h1.x, h1.y);
                Ar[4]  = __floats2half2_rn(h1.z, h1.w);
                Ar[5]  = __floats2half2_rn(h2.x, h2.y);
                Ar[6]  = __floats2half2_rn(h2.z, h2.w);
                Ar[7]  = __floats2half2_rn(h3.x, h3.y);
                Ar[8]  = __floats2half2_rn(h3.z, h3.w);
                Ar[9]  = __floats2half2_rn(h4.x, h4.y);
                Ar[10] = __floats2half2_rn(h4.z, h4.w);
                Ar[11] = __floats2half2_rn(1.0f, 0.0f);   // bias col 22
                Ar[12] = __floats2half2_rn(0.f, 0.f);
                Ar[13] = __floats2half2_rn(0.f, 0.f);
                Ar[14] = __floats2half2_rn(0.f, 0.f);
                Ar[15] = __floats2half2_rn(0.f, 0.f);
                const float4* cq = (const float4*)(cell + e * HDIM);
                float4* Cr = (float4*)&Cst[w][lane][0];
                Cr[0] = cq[0]; Cr[1] = cq[1]; Cr[2] = cq[2]; Cr[3] = cq[3]; Cr[4] = cq[4];
            }
            __syncwarp();

            // ---- layer 1: A fragments (K=32, 2 slices) ----
            uint32_t a1f[2][4];
            #pragma unroll
            for (int s = 0; s < 2; ++s) {
                a1f[s][0] = *(const uint32_t*)&A1s[w][g][16*s + 2*tig];
                a1f[s][1] = *(const uint32_t*)&A1s[w][g+8][16*s + 2*tig];
                a1f[s][2] = *(const uint32_t*)&A1s[w][g][16*s + 2*tig + 8];
                a1f[s][3] = *(const uint32_t*)&A1s[w][g+8][16*s + 2*tig + 8];
            }

            #pragma unroll 2
            for (int nt = 0; nt < 10; ++nt) {
                float d0 = 0.f, d1 = 0.f, d2 = 0.f, d3 = 0.f;
                #pragma unroll
                for (int s = 0; s < 2; ++s) {
                    uint32_t b0 = *(const uint32_t*)&B1s[8*nt + g][16*s + 2*tig];
                    uint32_t b1 = *(const uint32_t*)&B1s[8*nt + g][16*s + 2*tig + 8];
                    mma16816(d0, d1, d2, d3, a1f[s][0], a1f[s][1], a1f[s][2], a1f[s][3], b0, b1);
                }
                // exchange: even lane (tig even) sends (d2,d3)=(i,f) of row g+8,
                // receives (g,o) of row g. Odd lane sends (d0,d1)=(g,o) of row g,
                // receives (i,f) of row g+8 and uses ITS OWN d2,d3 for (g,o).
                const int j = 2*nt + (tig >> 1);
                float sh0 = __shfl_xor_sync(0xffffffffu, oddl ? d0 : d2, 1);
                float sh1 = __shfl_xor_sync(0xffffffffu, oddl ? d1 : d3, 1);
                float gi = oddl ? sh0 : d0;
                float gf = oddl ? sh1 : d1;
                float gg = oddl ? d2 : sh0;
                float go = oddl ? d3 : sh1;
                float cold = Cst[w][myrow][j];
                float cn = sigm_(gf) * cold + sigm_(gi) * tanh_(gg);
                float hn = sigm_(go) * tanh_(cn);
                Cst[w][myrow][j] = cn;
                Hst[w][myrow][j] = hn;
                A2s[w][myrow][j] = __float2half_rn(hn);
            }
            __syncwarp();

            // ---- store h_stack[0]/c_stack[0]; then refill stages for layer 2 ----
            for (int idx = lane; idx < 80; idx += 32) {
                int row = idx / 5, q = idx % 5;
                size_t e = base + row;
                *(float4*)&out[HBASE + e * HDIM + 4*q] = *(const float4*)&Hst[w][row][4*q];
                *(float4*)&out[CBASE + e * HDIM + 4*q] = *(const float4*)&Cst[w][row][4*q];
            }
            __syncwarp();
            for (int idx = lane; idx < 80; idx += 32) {
                int row = idx / 5, q = idx % 5;
                size_t e = base + row;
                float4 c1q = *(const float4*)&cell[(size_t)NB * HDIM + e * HDIM + 4*q];
                *(float4*)&Cst[w][row][4*q] = c1q;
                float4 h1q = *(const float4*)&hidden[(size_t)NB * HDIM + e * HDIM + 4*q];
                *(__half2*)&A2s[w][row][20 + 4*q]     = __floats2half2_rn(h1q.x, h1q.y);
                *(__half2*)&A2s[w][row][20 + 4*q + 2] = __floats2half2_rn(h1q.z, h1q.w);
            }
            if (lane < 16) {
                __half2* Ar = (__half2*)&A2s[w][lane][40];
                Ar[0] = __floats2half2_rn(1.0f, 0.0f);   // bias col 40
                Ar[1] = __floats2half2_rn(0.f, 0.f);
                Ar[2] = __floats2half2_rn(0.f, 0.f);
                Ar[3] = __floats2half2_rn(0.f, 0.f);
            }
            __syncwarp();

            // ---- layer 2: A fragments (K=48, 3 slices) ----
            uint32_t a2f[3][4];
            #pragma unroll
            for (int s = 0; s < 3; ++s) {
                a2f[s][0] = *(const uint32_t*)&A2s[w][g][16*s + 2*tig];
                a2f[s][1] = *(const uint32_t*)&A2s[w][g+8][16*s + 2*tig];
                a2f[s][2] = *(const uint32_t*)&A2s[w][g][16*s + 2*tig + 8];
                a2f[s][3] = *(const uint32_t*)&A2s[w][g+8][16*s + 2*tig + 8];
            }

            float o_acc = 0.f;
            #pragma unroll 2
            for (int nt = 0; nt < 10; ++nt) {
                float d0 = 0.f, d1 = 0.f, d2 = 0.f, d3 = 0.f;
                #pragma unroll
                for (int s = 0; s < 3; ++s) {
                    uint32_t b0 = *(const uint32_t*)&B2s[8*nt + g][16*s + 2*tig];
                    uint32_t b1 = *(const uint32_t*)&B2s[8*nt + g][16*s + 2*tig + 8];
                    mma16816(d0, d1, d2, d3, a2f[s][0], a2f[s][1], a2f[s][2], a2f[s][3], b0, b1);
                }
                const int j = 2*nt + (tig >> 1);
                float sh0 = __shfl_xor_sync(0xffffffffu, oddl ? d0 : d2, 1);
                float sh1 = __shfl_xor_sync(0xffffffffu, oddl ? d1 : d3, 1);
                float gi = oddl ? sh0 : d0;
                float gf = oddl ? sh1 : d1;
                float gg = oddl ? d2 : sh0;
                float go = oddl ? d3 : sh1;
                float cold = Cst[w][myrow][j];
                float cn = sigm_(gf) * cold + sigm_(gi) * tanh_(gg);
                float hn = sigm_(go) * tanh_(cn);
                Cst[w][myrow][j] = cn;
                Hst[w][myrow][j] = hn;
                o_acc += hn * Wos[j];
            }
            __syncwarp();

            // ---- store h_stack[1]/c_stack[1] ----
            for (int idx = lane; idx < 80; idx += 32) {
                int row = idx / 5, q = idx % 5;
                size_t e = base + row;
                *(float4*)&out[HBASE + (size_t)NB * HDIM + e * HDIM + 4*q] = *(const float4*)&Hst[w][row][4*q];
                *(float4*)&out[CBASE + (size_t)NB * HDIM + e * HDIM + 4*q] = *(const float4*)&Cst[w][row][4*q];
            }

            // ---- head: lanes tig0/tig2 hold even/odd j of row g;
            //            lanes tig1/tig3 hold even/odd j of row g+8 ----
            float s_o = o_acc + __shfl_xor_sync(0xffffffffu, o_acc, 2);
            if (tig == 0) {
                size_t e = base + g;
                float o = bos + s_o;
                float* o5 = out + e * 5;
                #pragma unroll
                for (int s = 0; s < 5; ++s) o5[s] = o * (float)(s + 1);
            }
            if (tig == 1) {
                size_t e = base + g + 8;
                float o = bos + s_o;
                float* o5 = out + e * 5;
                #pragma unroll
                for (int s = 0; s < 5; ++s) o5[s] = o * (float)(s + 1);
            }
            __syncwarp();
        }
    }
}

extern "C" void kernel_launch(void* const* d_in, const int* in_sizes, int n_in,
                              void* d_out, int out_size) {
    const float* inp    = (const float*)d_in[0];
    const float* hidden = (const float*)d_in[1];
    const float* cell   = (const float*)d_in[2];
    const float* W_ih1  = (const float*)d_in[3];
    const float* W_hh1  = (const float*)d_in[4];
    const float* b_ih1  = (const float*)d_in[5];
    const float* b_hh1  = (const float*)d_in[6];
    const float* W_ih2  = (const float*)d_in[7];
    const float* W_hh2  = (const float*)d_in[8];
    const float* b_ih2  = (const float*)d_in[9];
    const float* b_hh2  = (const float*)d_in[10];
    const float* W_out  = (const float*)d_in[11];
    const float* b_out  = (const float*)d_in[12];
    float* out = (float*)d_out;

    // 2048 blocks x 128 threads; each block: 4 tiles of 128 elements
    navi_mma<<<2048, 128>>>(inp, hidden, cell,
                            W_ih1, W_hh1, b_ih1, b_hh1,
                            W_ih2, W_hh2, b_ih2, b_hh2,
                            W_out, b_out, out);
}

// round 14
// speedup vs baseline: 4.6870x; 1.1528x over previous
#include <cuda_runtime.h>
#include <cuda_fp16.h>
#include <cstdint>

// LinearNavigator via warp-level HMMA (mma.sync m16n8k16, f16 in / f32 accum).
// R14 (= R13 resubmit): prefetch layer-2 state loads to phase A (overlap with
// layer-1 compute), fused store+refill of Cst, precomputed staging indices.
// out layout: out[B,5], h_stack[2,B,20], c_stack[2,B,20]

#define NB 1048576
#define HDIM 20
#define HBASE ((size_t)5 * NB)
#define CBASE (HBASE + (size_t)2 * NB * HDIM)

__device__ __forceinline__ float sigm_(float x) {
    return __fdividef(1.0f, 1.0f + __expf(-x));
}
__device__ __forceinline__ float tanh_(float x) {
    float e = __expf(2.0f * x);
    return 1.0f - __fdividef(2.0f, e + 1.0f);
}

__device__ __forceinline__ void mma16816(float& d0, float& d1, float& d2, float& d3,
                                         uint32_t a0, uint32_t a1, uint32_t a2, uint32_t a3,
                                         uint32_t b0, uint32_t b1) {
    asm volatile(
        "mma.sync.aligned.m16n8k16.row.col.f32.f16.f16.f32 "
        "{%0,%1,%2,%3}, {%4,%5,%6,%7}, {%8,%9}, {%0,%1,%2,%3};"
        : "+f"(d0), "+f"(d1), "+f"(d2), "+f"(d3)
        : "r"(a0), "r"(a1), "r"(a2), "r"(a3), "r"(b0), "r"(b1));
}

__global__ __launch_bounds__(128)
void navi_mma(const float* __restrict__ inp, const float* __restrict__ hidden,
              const float* __restrict__ cell,
              const float* __restrict__ W_ih1, const float* __restrict__ W_hh1,
              const float* __restrict__ b_ih1, const float* __restrict__ b_hh1,
              const float* __restrict__ W_ih2, const float* __restrict__ W_hh2,
              const float* __restrict__ b_ih2, const float* __restrict__ b_hh2,
              const float* __restrict__ W_out, const float* __restrict__ b_out,
              float* __restrict__ out)
{
    __shared__ __align__(16) __half B1s[80][40];
    __shared__ __align__(16) __half B2s[80][56];
    __shared__ float  Wos[20];
    __shared__ float  bos;
    __shared__ __align__(16) __half A1s[4][16][40];
    __shared__ __align__(16) __half A2s[4][16][56];
    __shared__ __align__(16) float  Cst[4][16][20];
    __shared__ __align__(16) float  Hst[4][16][20];

    const int t = threadIdx.x;
    const int w = t >> 5;
    const int lane = t & 31;
    const int g = lane >> 2;
    const int tig = lane & 3;
    const bool oddl = (tig & 1);
    const int myrow = oddl ? g + 8 : g;

    // staging index pairs for idx = lane, lane+32, lane+64 (<80)
    const int r0 = lane / 5,        q0 = lane % 5;
    const int r1 = (lane + 32) / 5, q1 = (lane + 32) % 5;
    const int r2 = (lane + 64) / 5, q2 = (lane + 64) % 5;   // valid iff lane < 16
    const bool has2 = (lane < 16);

    // ---------------- one-time weight fill ----------------
    {
        __half2* z1 = (__half2*)&B1s[0][0];
        for (int i = t; i < 80 * 20; i += 128) z1[i] = __floats2half2_rn(0.f, 0.f);
        __half2* z2 = (__half2*)&B2s[0][0];
        for (int i = t; i < 80 * 28; i += 128) z2[i] = __floats2half2_rn(0.f, 0.f);
    }
    __syncthreads();
    for (int i = t; i < 1600; i += 128) {
        int r = i / 20, k = i % 20;
        int n = 4 * (r % 20) + (r / 20);
        B1s[n][2 + k] = __float2half_rn(W_hh1[i]);
        B2s[n][k]      = __float2half_rn(W_ih2[i]);
        B2s[n][20 + k] = __float2half_rn(W_hh2[i]);
    }
    for (int i = t; i < 160; i += 128) {
        int r = i / 2, k = i % 2;
        int n = 4 * (r % 20) + (r / 20);
        B1s[n][k] = __float2half_rn(W_ih1[i]);
    }
    for (int i = t; i < 80; i += 128) {
        int n = 4 * (i % 20) + (i / 20);
        B1s[n][22] = __float2half_rn(b_ih1[i] + b_hh1[i]);
        B2s[n][40] = __float2half_rn(b_ih2[i] + b_hh2[i]);
    }
    if (t < 20) Wos[t] = W_out[t];
    if (t == 20) bos = b_out[0];
    __syncthreads();

    // ---------------- tile loop: 8 m-tiles of 16 elements per warp ----------------
    #pragma unroll 1
    for (int itile = 0; itile < 8; ++itile) {
        const int it = itile >> 1, mt = itile & 1;
        const size_t base = ((size_t)blockIdx.x * 4 + it) * 128 + (size_t)w * 32 + mt * 16;

        // ---- phase A0: PREFETCH layer-2 state into registers (all lanes) ----
        const float* c1base = cell   + (size_t)NB * HDIM;
        const float* h1base = hidden + (size_t)NB * HDIM;
        float4 c1a = *(const float4*)&c1base[(base + r0) * HDIM + 4*q0];
        float4 h1a = *(const float4*)&h1base[(base + r0) * HDIM + 4*q0];
        float4 c1b = *(const float4*)&c1base[(base + r1) * HDIM + 4*q1];
        float4 h1b = *(const float4*)&h1base[(base + r1) * HDIM + 4*q1];
        float4 c1c = make_float4(0.f, 0.f, 0.f, 0.f);
        float4 h1c = make_float4(0.f, 0.f, 0.f, 0.f);
        if (has2) {
            c1c = *(const float4*)&c1base[(base + r2) * HDIM + 4*q2];
            h1c = *(const float4*)&h1base[(base + r2) * HDIM + 4*q2];
        }

        // ---- phase A: preproc + A1 fill + c0 stage (lanes 0..15) ----
        if (lane < 16) {
            const size_t e = base + lane;
            const float v = inp[e];
            const float av = fabsf(v);
            float x0, x1;
            if (av >= 4.5399929762484854e-05f) {
                x0 = __logf(av + 1e-8f) * 0.1f;
                x1 = (v > 0.0f) ? 1.0f : -1.0f;
            } else {
                x0 = -1.0f;
                x1 = 22026.465794806718f * v;
            }
            const float4* hq = (const float4*)(hidden + e * HDIM);
            float4 h0 = hq[0], h1 = hq[1], h2 = hq[2], h3 = hq[3], h4 = hq[4];
            __half2* Ar = (__half2*)&A1s[w][lane][0];
            Ar[0]  = __floats2half2_rn(x0, x1);
            Ar[1]  = __floats2half2_rn(h0.x, h0.y);
            Ar[2]  = __floats2half2_rn(h0.z, h0.w);
            Ar[3]  = __floats2half2_rn(h1.x, h1.y);
            Ar[4]  = __floats2half2_rn(h1.z, h1.w);
            Ar[5]  = __floats2half2_rn(h2.x, h2.y);
            Ar[6]  = __floats2half2_rn(h2.z, h2.w);
            Ar[7]  = __floats2half2_rn(h3.x, h3.y);
            Ar[8]  = __floats2half2_rn(h3.z, h3.w);
            Ar[9]  = __floats2half2_rn(h4.x, h4.y);
            Ar[10] = __floats2half2_rn(h4.z, h4.w);
            Ar[11] = __floats2half2_rn(1.0f, 0.0f);   // bias col 22
            Ar[12] = __floats2half2_rn(0.f, 0.f);
            Ar[13] = __floats2half2_rn(0.f, 0.f);
            Ar[14] = __floats2half2_rn(0.f, 0.f);
            Ar[15] = __floats2half2_rn(0.f, 0.f);
            const float4* cq = (const float4*)(cell + e * HDIM);
            float4* Cr = (float4*)&Cst[w][lane][0];
            Cr[0] = cq[0]; Cr[1] = cq[1]; Cr[2] = cq[2]; Cr[3] = cq[3]; Cr[4] = cq[4];
        }
        __syncwarp();

        // ---- layer 1: A fragments (K=32, 2 slices) ----
        uint32_t a1f[2][4];
        #pragma unroll
        for (int s = 0; s < 2; ++s) {
            a1f[s][0] = *(const uint32_t*)&A1s[w][g][16*s + 2*tig];
            a1f[s][1] = *(const uint32_t*)&A1s[w][g+8][16*s + 2*tig];
            a1f[s][2] = *(const uint32_t*)&A1s[w][g][16*s + 2*tig + 8];
            a1f[s][3] = *(const uint32_t*)&A1s[w][g+8][16*s + 2*tig + 8];
        }

        #pragma unroll 2
        for (int nt = 0; nt < 10; ++nt) {
            float d0 = 0.f, d1 = 0.f, d2 = 0.f, d3 = 0.f;
            #pragma unroll
            for (int s = 0; s < 2; ++s) {
                uint32_t b0 = *(const uint32_t*)&B1s[8*nt + g][16*s + 2*tig];
                uint32_t b1 = *(const uint32_t*)&B1s[8*nt + g][16*s + 2*tig + 8];
                mma16816(d0, d1, d2, d3, a1f[s][0], a1f[s][1], a1f[s][2], a1f[s][3], b0, b1);
            }
            const int j = 2*nt + (tig >> 1);
            float sh0 = __shfl_xor_sync(0xffffffffu, oddl ? d0 : d2, 1);
            float sh1 = __shfl_xor_sync(0xffffffffu, oddl ? d1 : d3, 1);
            float gi = oddl ? sh0 : d0;
            float gf = oddl ? sh1 : d1;
            float gg = oddl ? d2 : sh0;
            float go = oddl ? d3 : sh1;
            float cold = Cst[w][myrow][j];
            float cn = sigm_(gf) * cold + sigm_(gi) * tanh_(gg);
            float hn = sigm_(go) * tanh_(cn);
            Cst[w][myrow][j] = cn;
            Hst[w][myrow][j] = hn;
            A2s[w][myrow][j] = __float2half_rn(hn);
        }
        __syncwarp();

        // ---- fused: store h0/c0; refill Cst<-c1, A2s<-h1 (same-lane addresses) ----
        {
            size_t e0 = base + r0, e1 = base + r1;
            *(float4*)&out[HBASE + e0 * HDIM + 4*q0] = *(const float4*)&Hst[w][r0][4*q0];
            *(float4*)&out[CBASE + e0 * HDIM + 4*q0] = *(const float4*)&Cst[w][r0][4*q0];
            *(float4*)&Cst[w][r0][4*q0] = c1a;
            *(__half2*)&A2s[w][r0][20 + 4*q0]     = __floats2half2_rn(h1a.x, h1a.y);
            *(__half2*)&A2s[w][r0][20 + 4*q0 + 2] = __floats2half2_rn(h1a.z, h1a.w);
            *(float4*)&out[HBASE + e1 * HDIM + 4*q1] = *(const float4*)&Hst[w][r1][4*q1];
            *(float4*)&out[CBASE + e1 * HDIM + 4*q1] = *(const float4*)&Cst[w][r1][4*q1];
            *(float4*)&Cst[w][r1][4*q1] = c1b;
            *(__half2*)&A2s[w][r1][20 + 4*q1]     = __floats2half2_rn(h1b.x, h1b.y);
            *(__half2*)&A2s[w][r1][20 + 4*q1 + 2] = __floats2half2_rn(h1b.z, h1b.w);
            if (has2) {
                size_t e2 = base + r2;
                *(float4*)&out[HBASE + e2 * HDIM + 4*q2] = *(const float4*)&Hst[w][r2][4*q2];
                *(float4*)&out[CBASE + e2 * HDIM + 4*q2] = *(const float4*)&Cst[w][r2][4*q2];
                *(float4*)&Cst[w][r2][4*q2] = c1c;
                *(__half2*)&A2s[w][r2][20 + 4*q2]     = __floats2half2_rn(h1c.x, h1c.y);
                *(__half2*)&A2s[w][r2][20 + 4*q2 + 2] = __floats2half2_rn(h1c.z, h1c.w);
                // bias col 40 + zero pad 41..47 for row `lane`
                __half2* Ar = (__half2*)&A2s[w][lane][40];
                Ar[0] = __floats2half2_rn(1.0f, 0.0f);
                Ar[1] = __floats2half2_rn(0.f, 0.f);
                Ar[2] = __floats2half2_rn(0.f, 0.f);
                Ar[3] = __floats2half2_rn(0.f, 0.f);
            }
        }
        __syncwarp();

        // ---- layer 2: A fragments (K=48, 3 slices) ----
        uint32_t a2f[3][4];
        #pragma unroll
        for (int s = 0; s < 3; ++s) {
            a2f[s][0] = *(const uint32_t*)&A2s[w][g][16*s + 2*tig];
            a2f[s][1] = *(const uint32_t*)&A2s[w][g+8][16*s + 2*tig];
            a2f[s][2] = *(const uint32_t*)&A2s[w][g][16*s + 2*tig + 8];
            a2f[s][3] = *(const uint32_t*)&A2s[w][g+8][16*s + 2*tig + 8];
        }

        float o_acc = 0.f;
        #pragma unroll 2
        for (int nt = 0; nt < 10; ++nt) {
            float d0 = 0.f, d1 = 0.f, d2 = 0.f, d3 = 0.f;
            #pragma unroll
            for (int s = 0; s < 3; ++s) {
                uint32_t b0 = *(const uint32_t*)&B2s[8*nt + g][16*s + 2*tig];
                uint32_t b1 = *(const uint32_t*)&B2s[8*nt + g][16*s + 2*tig + 8];
                mma16816(d0, d1, d2, d3, a2f[s][0], a2f[s][1], a2f[s][2], a2f[s][3], b0, b1);
            }
            const int j = 2*nt + (tig >> 1);
            float sh0 = __shfl_xor_sync(0xffffffffu, oddl ? d0 : d2, 1);
            float sh1 = __shfl_xor_sync(0xffffffffu, oddl ? d1 : d3, 1);
            float gi = oddl ? sh0 : d0;
            float gf = oddl ? sh1 : d1;
            float gg = oddl ? d2 : sh0;
            float go = oddl ? d3 : sh1;
            float cold = Cst[w][myrow][j];
            float cn = sigm_(gf) * cold + sigm_(gi) * tanh_(gg);
            float hn = sigm_(go) * tanh_(cn);
            Cst[w][myrow][j] = cn;
            Hst[w][myrow][j] = hn;
            o_acc += hn * Wos[j];
        }
        __syncwarp();

        // ---- store h_stack[1]/c_stack[1] ----
        {
            size_t e0 = base + r0, e1 = base + r1;
            *(float4*)&out[HBASE + (size_t)NB * HDIM + e0 * HDIM + 4*q0] = *(const float4*)&Hst[w][r0][4*q0];
            *(float4*)&out[CBASE + (size_t)NB * HDIM + e0 * HDIM + 4*q0] = *(const float4*)&Cst[w][r0][4*q0];
            *(float4*)&out[HBASE + (size_t)NB * HDIM + e1 * HDIM + 4*q1] = *(const float4*)&Hst[w][r1][4*q1];
            *(float4*)&out[CBASE + (size_t)NB * HDIM + e1 * HDIM + 4*q1] = *(const float4*)&Cst[w][r1][4*q1];
            if (has2) {
                size_t e2 = base + r2;
                *(float4*)&out[HBASE + (size_t)NB * HDIM + e2 * HDIM + 4*q2] = *(const float4*)&Hst[w][r2][4*q2];
                *(float4*)&out[CBASE + (size_t)NB * HDIM + e2 * HDIM + 4*q2] = *(const float4*)&Cst[w][r2][4*q2];
            }
        }

        // ---- head: lanes tig0/tig2 = row g; tig1/tig3 = row g+8 ----
        float s_o = o_acc + __shfl_xor_sync(0xffffffffu, o_acc, 2);
        if (tig == 0) {
            size_t e = base + g;
            float o = bos + s_o;
            float* o5 = out + e * 5;
            #pragma unroll
            for (int s = 0; s < 5; ++s) o5[s] = o * (float)(s + 1);
        }
        if (tig == 1) {
            size_t e = base + g + 8;
            float o = bos + s_o;
            float* o5 = out + e * 5;
            #pragma unroll
            for (int s = 0; s < 5; ++s) o5[s] = o * (float)(s + 1);
        }
        __syncwarp();
    }
}

extern "C" void kernel_launch(void* const* d_in, const int* in_sizes, int n_in,
                              void* d_out, int out_size) {
    const float* inp    = (const float*)d_in[0];
    const float* hidden = (const float*)d_in[1];
    const float* cell   = (const float*)d_in[2];
    const float* W_ih1  = (const float*)d_in[3];
    const float* W_hh1  = (const float*)d_in[4];
    const float* b_ih1  = (const float*)d_in[5];
    const float* b_hh1  = (const float*)d_in[6];
    const float* W_ih2  = (const float*)d_in[7];
    const float* W_hh2  = (const float*)d_in[8];
    const float* b_ih2  = (const float*)d_in[9];
    const float* b_hh2  = (const float*)d_in[10];
    const float* W_out  = (const float*)d_in[11];
    const float* b_out  = (const float*)d_in[12];
    float* out = (float*)d_out;

    navi_mma<<<2048, 128>>>(inp, hidden, cell,
                            W_ih1, W_hh1, b_ih1, b_hh1,
                            W_ih2, W_hh2, b_ih2, b_hh2,
                            W_out, b_out, out);
}

// round 16
// speedup vs baseline: 5.1499x; 1.0988x over previous
#include <cuda_runtime.h>
#include <cuda_fp16.h>
#include <cstdint>

// LinearNavigator via warp-level HMMA (mma.sync m16n8k16, f16 in / f32 accum).
// R15: R14 + MUFU.TANH activations (tanh.approx.f32; sigmoid = 0.5*tanh(0.5x)+0.5)
// -> 5 MUFU/cell instead of 10, shorter epilogue chains.
// out layout: out[B,5], h_stack[2,B,20], c_stack[2,B,20]

#define NB 1048576
#define HDIM 20
#define HBASE ((size_t)5 * NB)
#define CBASE (HBASE + (size_t)2 * NB * HDIM)

__device__ __forceinline__ float tanhap_(float x) {
    float y; asm("tanh.approx.f32 %0, %1;" : "=f"(y) : "f"(x)); return y;
}
__device__ __forceinline__ float sigm_(float x) {
    return fmaf(0.5f, tanhap_(0.5f * x), 0.5f);
}

__device__ __forceinline__ void mma16816(float& d0, float& d1, float& d2, float& d3,
                                         uint32_t a0, uint32_t a1, uint32_t a2, uint32_t a3,
                                         uint32_t b0, uint32_t b1) {
    asm volatile(
        "mma.sync.aligned.m16n8k16.row.col.f32.f16.f16.f32 "
        "{%0,%1,%2,%3}, {%4,%5,%6,%7}, {%8,%9}, {%0,%1,%2,%3};"
        : "+f"(d0), "+f"(d1), "+f"(d2), "+f"(d3)
        : "r"(a0), "r"(a1), "r"(a2), "r"(a3), "r"(b0), "r"(b1));
}

__global__ __launch_bounds__(128)
void navi_mma(const float* __restrict__ inp, const float* __restrict__ hidden,
              const float* __restrict__ cell,
              const float* __restrict__ W_ih1, const float* __restrict__ W_hh1,
              const float* __restrict__ b_ih1, const float* __restrict__ b_hh1,
              const float* __restrict__ W_ih2, const float* __restrict__ W_hh2,
              const float* __restrict__ b_ih2, const float* __restrict__ b_hh2,
              const float* __restrict__ W_out, const float* __restrict__ b_out,
              float* __restrict__ out)
{
    __shared__ __align__(16) __half B1s[80][40];
    __shared__ __align__(16) __half B2s[80][56];
    __shared__ float  Wos[20];
    __shared__ float  bos;
    __shared__ __align__(16) __half A1s[4][16][40];
    __shared__ __align__(16) __half A2s[4][16][56];
    __shared__ __align__(16) float  Cst[4][16][20];
    __shared__ __align__(16) float  Hst[4][16][20];

    const int t = threadIdx.x;
    const int w = t >> 5;
    const int lane = t & 31;
    const int g = lane >> 2;
    const int tig = lane & 3;
    const bool oddl = (tig & 1);
    const int myrow = oddl ? g + 8 : g;

    // staging index pairs for idx = lane, lane+32, lane+64 (<80)
    const int r0 = lane / 5,        q0 = lane % 5;
    const int r1 = (lane + 32) / 5, q1 = (lane + 32) % 5;
    const int r2 = (lane + 64) / 5, q2 = (lane + 64) % 5;   // valid iff lane < 16
    const bool has2 = (lane < 16);

    // ---------------- one-time weight fill ----------------
    {
        __half2* z1 = (__half2*)&B1s[0][0];
        for (int i = t; i < 80 * 20; i += 128) z1[i] = __floats2half2_rn(0.f, 0.f);
        __half2* z2 = (__half2*)&B2s[0][0];
        for (int i = t; i < 80 * 28; i += 128) z2[i] = __floats2half2_rn(0.f, 0.f);
    }
    __syncthreads();
    for (int i = t; i < 1600; i += 128) {
        int r = i / 20, k = i % 20;
        int n = 4 * (r % 20) + (r / 20);
        B1s[n][2 + k] = __float2half_rn(W_hh1[i]);
        B2s[n][k]      = __float2half_rn(W_ih2[i]);
        B2s[n][20 + k] = __float2half_rn(W_hh2[i]);
    }
    for (int i = t; i < 160; i += 128) {
        int r = i / 2, k = i % 2;
        int n = 4 * (r % 20) + (r / 20);
        B1s[n][k] = __float2half_rn(W_ih1[i]);
    }
    for (int i = t; i < 80; i += 128) {
        int n = 4 * (i % 20) + (i / 20);
        B1s[n][22] = __float2half_rn(b_ih1[i] + b_hh1[i]);
        B2s[n][40] = __float2half_rn(b_ih2[i] + b_hh2[i]);
    }
    if (t < 20) Wos[t] = W_out[t];
    if (t == 20) bos = b_out[0];
    __syncthreads();

    // ---------------- tile loop: 8 m-tiles of 16 elements per warp ----------------
    #pragma unroll 1
    for (int itile = 0; itile < 8; ++itile) {
        const int it = itile >> 1, mt = itile & 1;
        const size_t base = ((size_t)blockIdx.x * 4 + it) * 128 + (size_t)w * 32 + mt * 16;

        // ---- phase A0: PREFETCH layer-2 state into registers (all lanes) ----
        const float* c1base = cell   + (size_t)NB * HDIM;
        const float* h1base = hidden + (size_t)NB * HDIM;
        float4 c1a = *(const float4*)&c1base[(base + r0) * HDIM + 4*q0];
        float4 h1a = *(const float4*)&h1base[(base + r0) * HDIM + 4*q0];
        float4 c1b = *(const float4*)&c1base[(base + r1) * HDIM + 4*q1];
        float4 h1b = *(const float4*)&h1base[(base + r1) * HDIM + 4*q1];
        float4 c1c = make_float4(0.f, 0.f, 0.f, 0.f);
        float4 h1c = make_float4(0.f, 0.f, 0.f, 0.f);
        if (has2) {
            c1c = *(const float4*)&c1base[(base + r2) * HDIM + 4*q2];
            h1c = *(const float4*)&h1base[(base + r2) * HDIM + 4*q2];
        }

        // ---- phase A: preproc + A1 fill + c0 stage (lanes 0..15) ----
        if (lane < 16) {
            const size_t e = base + lane;
            const float v = inp[e];
            const float av = fabsf(v);
            float x0, x1;
            if (av >= 4.5399929762484854e-05f) {
                x0 = __logf(av + 1e-8f) * 0.1f;
                x1 = (v > 0.0f) ? 1.0f : -1.0f;
            } else {
                x0 = -1.0f;
                x1 = 22026.465794806718f * v;
            }
            const float4* hq = (const float4*)(hidden + e * HDIM);
            float4 h0 = hq[0], h1 = hq[1], h2 = hq[2], h3 = hq[3], h4 = hq[4];
            __half2* Ar = (__half2*)&A1s[w][lane][0];
            Ar[0]  = __floats2half2_rn(x0, x1);
            Ar[1]  = __floats2half2_rn(h0.x, h0.y);
            Ar[2]  = __floats2half2_rn(h0.z, h0.w);
            Ar[3]  = __floats2half2_rn(h1.x, h1.y);
            Ar[4]  = __floats2half2_rn(h1.z, h1.w);
            Ar[5]  = __floats2half2_rn(h2.x, h2.y);
            Ar[6]  = __floats2half2_rn(h2.z, h2.w);
            Ar[7]  = __floats2half2_rn(h3.x, h3.y);
            Ar[8]  = __floats2half2_rn(h3.z, h3.w);
            Ar[9]  = __floats2half2_rn(h4.x, h4.y);
            Ar[10] = __floats2half2_rn(h4.z, h4.w);
            Ar[11] = __floats2half2_rn(1.0f, 0.0f);   // bias col 22
            Ar[12] = __floats2half2_rn(0.f, 0.f);
            Ar[13] = __floats2half2_rn(0.f, 0.f);
            Ar[14] = __floats2half2_rn(0.f, 0.f);
            Ar[15] = __floats2half2_rn(0.f, 0.f);
            const float4* cq = (const float4*)(cell + e * HDIM);
            float4* Cr = (float4*)&Cst[w][lane][0];
            Cr[0] = cq[0]; Cr[1] = cq[1]; Cr[2] = cq[2]; Cr[3] = cq[3]; Cr[4] = cq[4];
        }
        __syncwarp();

        // ---- layer 1: A fragments (K=32, 2 slices) ----
        uint32_t a1f[2][4];
        #pragma unroll
        for (int s = 0; s < 2; ++s) {
            a1f[s][0] = *(const uint32_t*)&A1s[w][g][16*s + 2*tig];
            a1f[s][1] = *(const uint32_t*)&A1s[w][g+8][16*s + 2*tig];
            a1f[s][2] = *(const uint32_t*)&A1s[w][g][16*s + 2*tig + 8];
            a1f[s][3] = *(const uint32_t*)&A1s[w][g+8][16*s + 2*tig + 8];
        }

        #pragma unroll 2
        for (int nt = 0; nt < 10; ++nt) {
            float d0 = 0.f, d1 = 0.f, d2 = 0.f, d3 = 0.f;
            #pragma unroll
            for (int s = 0; s < 2; ++s) {
                uint32_t b0 = *(const uint32_t*)&B1s[8*nt + g][16*s + 2*tig];
                uint32_t b1 = *(const uint32_t*)&B1s[8*nt + g][16*s + 2*tig + 8];
                mma16816(d0, d1, d2, d3, a1f[s][0], a1f[s][1], a1f[s][2], a1f[s][3], b0, b1);
            }
            const int j = 2*nt + (tig >> 1);
            float sh0 = __shfl_xor_sync(0xffffffffu, oddl ? d0 : d2, 1);
            float sh1 = __shfl_xor_sync(0xffffffffu, oddl ? d1 : d3, 1);
            float gi = oddl ? sh0 : d0;
            float gf = oddl ? sh1 : d1;
            float gg = oddl ? d2 : sh0;
            float go = oddl ? d3 : sh1;
            float cold = Cst[w][myrow][j];
            float cn = sigm_(gf) * cold + sigm_(gi) * tanhap_(gg);
            float hn = sigm_(go) * tanhap_(cn);
            Cst[w][myrow][j] = cn;
            Hst[w][myrow][j] = hn;
            A2s[w][myrow][j] = __float2half_rn(hn);
        }
        __syncwarp();

        // ---- fused: store h0/c0; refill Cst<-c1, A2s<-h1 (same-lane addresses) ----
        {
            size_t e0 = base + r0, e1 = base + r1;
            *(float4*)&out[HBASE + e0 * HDIM + 4*q0] = *(const float4*)&Hst[w][r0][4*q0];
            *(float4*)&out[CBASE + e0 * HDIM + 4*q0] = *(const float4*)&Cst[w][r0][4*q0];
            *(float4*)&Cst[w][r0][4*q0] = c1a;
            *(__half2*)&A2s[w][r0][20 + 4*q0]     = __floats2half2_rn(h1a.x, h1a.y);
            *(__half2*)&A2s[w][r0][20 + 4*q0 + 2] = __floats2half2_rn(h1a.z, h1a.w);
            *(float4*)&out[HBASE + e1 * HDIM + 4*q1] = *(const float4*)&Hst[w][r1][4*q1];
            *(float4*)&out[CBASE + e1 * HDIM + 4*q1] = *(const float4*)&Cst[w][r1][4*q1];
            *(float4*)&Cst[w][r1][4*q1] = c1b;
            *(__half2*)&A2s[w][r1][20 + 4*q1]     = __floats2half2_rn(h1b.x, h1b.y);
            *(__half2*)&A2s[w][r1][20 + 4*q1 + 2] = __floats2half2_rn(h1b.z, h1b.w);
            if (has2) {
                size_t e2 = base + r2;
                *(float4*)&out[HBASE + e2 * HDIM + 4*q2] = *(const float4*)&Hst[w][r2][4*q2];
                *(float4*)&out[CBASE + e2 * HDIM + 4*q2] = *(const float4*)&Cst[w][r2][4*q2];
                *(float4*)&Cst[w][r2][4*q2] = c1c;
                *(__half2*)&A2s[w][r2][20 + 4*q2]     = __floats2half2_rn(h1c.x, h1c.y);
                *(__half2*)&A2s[w][r2][20 + 4*q2 + 2] = __floats2half2_rn(h1c.z, h1c.w);
                // bias col 40 + zero pad 41..47 for row `lane`
                __half2* Ar = (__half2*)&A2s[w][lane][40];
                Ar[0] = __floats2half2_rn(1.0f, 0.0f);
                Ar[1] = __floats2half2_rn(0.f, 0.f);
                Ar[2] = __floats2half2_rn(0.f, 0.f);
                Ar[3] = __floats2half2_rn(0.f, 0.f);
            }
        }
        __syncwarp();

        // ---- layer 2: A fragments (K=48, 3 slices) ----
        uint32_t a2f[3][4];
        #pragma unroll
        for (int s = 0; s < 3; ++s) {
            a2f[s][0] = *(const uint32_t*)&A2s[w][g][16*s + 2*tig];
            a2f[s][1] = *(const uint32_t*)&A2s[w][g+8][16*s + 2*tig];
            a2f[s][2] = *(const uint32_t*)&A2s[w][g][16*s + 2*tig + 8];
            a2f[s][3] = *(const uint32_t*)&A2s[w][g+8][16*s + 2*tig + 8];
        }

        float o_acc = 0.f;
        #pragma unroll 2
        for (int nt = 0; nt < 10; ++nt) {
            float d0 = 0.f, d1 = 0.f, d2 = 0.f, d3 = 0.f;
            #pragma unroll
            for (int s = 0; s < 3; ++s) {
                uint32_t b0 = *(const uint32_t*)&B2s[8*nt + g][16*s + 2*tig];
                uint32_t b1 = *(const uint32_t*)&B2s[8*nt + g][16*s + 2*tig + 8];
                mma16816(d0, d1, d2, d3, a2f[s][0], a2f[s][1], a2f[s][2], a2f[s][3], b0, b1);
            }
            const int j = 2*nt + (tig >> 1);
            float sh0 = __shfl_xor_sync(0xffffffffu, oddl ? d0 : d2, 1);
            float sh1 = __shfl_xor_sync(0xffffffffu, oddl ? d1 : d3, 1);
            float gi = oddl ? sh0 : d0;
            float gf = oddl ? sh1 : d1;
            float gg = oddl ? d2 : sh0;
            float go = oddl ? d3 : sh1;
            float cold = Cst[w][myrow][j];
            float cn = sigm_(gf) * cold + sigm_(gi) * tanhap_(gg);
            float hn = sigm_(go) * tanhap_(cn);
            Cst[w][myrow][j] = cn;
            Hst[w][myrow][j] = hn;
            o_acc += hn * Wos[j];
        }
        __syncwarp();

        // ---- store h_stack[1]/c_stack[1] ----
        {
            size_t e0 = base + r0, e1 = base + r1;
            *(float4*)&out[HBASE + (size_t)NB * HDIM + e0 * HDIM + 4*q0] = *(const float4*)&Hst[w][r0][4*q0];
            *(float4*)&out[CBASE + (size_t)NB * HDIM + e0 * HDIM + 4*q0] = *(const float4*)&Cst[w][r0][4*q0];
            *(float4*)&out[HBASE + (size_t)NB * HDIM + e1 * HDIM + 4*q1] = *(const float4*)&Hst[w][r1][4*q1];
            *(float4*)&out[CBASE + (size_t)NB * HDIM + e1 * HDIM + 4*q1] = *(const float4*)&Cst[w][r1][4*q1];
            if (has2) {
                size_t e2 = base + r2;
                *(float4*)&out[HBASE + (size_t)NB * HDIM + e2 * HDIM + 4*q2] = *(const float4*)&Hst[w][r2][4*q2];
                *(float4*)&out[CBASE + (size_t)NB * HDIM + e2 * HDIM + 4*q2] = *(const float4*)&Cst[w][r2][4*q2];
            }
        }

        // ---- head: lanes tig0/tig2 = row g; tig1/tig3 = row g+8 ----
        float s_o = o_acc + __shfl_xor_sync(0xffffffffu, o_acc, 2);
        if (tig == 0) {
            size_t e = base + g;
            float o = bos + s_o;
            float* o5 = out + e * 5;
            #pragma unroll
            for (int s = 0; s < 5; ++s) o5[s] = o * (float)(s + 1);
        }
        if (tig == 1) {
            size_t e = base + g + 8;
            float o = bos + s_o;
            float* o5 = out + e * 5;
            #pragma unroll
            for (int s = 0; s < 5; ++s) o5[s] = o * (float)(s + 1);
        }
        __syncwarp();
    }
}

extern "C" void kernel_launch(void* const* d_in, const int* in_sizes, int n_in,
                              void* d_out, int out_size) {
    const float* inp    = (const float*)d_in[0];
    const float* hidden = (const float*)d_in[1];
    const float* cell   = (const float*)d_in[2];
    const float* W_ih1  = (const float*)d_in[3];
    const float* W_hh1  = (const float*)d_in[4];
    const float* b_ih1  = (const float*)d_in[5];
    const float* b_hh1  = (const float*)d_in[6];
    const float* W_ih2  = (const float*)d_in[7];
    const float* W_hh2  = (const float*)d_in[8];
    const float* b_ih2  = (const float*)d_in[9];
    const float* b_hh2  = (const float*)d_in[10];
    const float* W_out  = (const float*)d_in[11];
    const float* b_out  = (const float*)d_in[12];
    float* out = (float*)d_out;

    navi_mma<<<2048, 128>>>(inp, hidden, cell,
                            W_ih1, W_hh1, b_ih1, b_hh1,
                            W_ih2, W_hh2, b_ih2, b_hh2,
                            W_out, b_out, out);
}